// round 5
// baseline (speedup 1.0000x reference)
#include <cuda_runtime.h>
#include <cstdint>

// SPIL layer, fused single kernel — sm_103 (non-'a') compatible: mma.sync tf32.
// B=8, N=4096, K=32, C=128, H=64, P=32. One CTA = 4 points (128 neighbor rows).
// theta projection: mma.sync.m16n8k8 tf32, warp w owns D rows [16w,16w+16).
// z projection hoisted out of K: out = (sum_k W_k nf_k) @ z_w + (sum W) z_b.

#define KNN 32
#define C_ 128
#define H_ 64

static constexpr int SA_STR = 132;   // A row stride in floats (pad 4: conflict-free frags)
static constexpr int SD_STR = 65;    // D row stride in floats (odd: conflict-free epilogue)
static constexpr int SM_A   = 0;                 // 128 x 132 fp32 = 67584 B
static constexpr int SM_B   = 67584;             // Bp packed tf32 (32768 B), then Ds (33280 B)
static constexpr int SM_SCAL = 100864;           // scalar float region
// float offsets inside scalar region
static constexpr int OF_CF  = 0;     // center_features 4x128
static constexpr int OF_NX  = 512;   // neighbor_xyz 4x32x3
static constexpr int OF_CX  = 896;   // center_xyz 4x3
static constexpr int OF_FI  = 908;   // feat_i 4x64
static constexpr int OF_W   = 1164;  // W_ij 128
static constexpr int OF_SW  = 1292;  // sumW 4
static constexpr int OF_SI  = 1296;  // s_i 4
static constexpr int OF_AGG = 1300;  // agg 4x128
static constexpr int OF_M1W = 1812, OF_M1B = 1908, OF_M2W = 1940, OF_M2B = 2036;
static constexpr int OF_PSW = 2068, OF_THB = 2132, OF_ZB = 2196, OF_PHB = 2260, OF_PSB = 2324;
static constexpr int OF_P   = 2328;  // cc-split partials [cc][p][64] = 1024 floats (reused)
static constexpr int SMEM_BYTES = SM_SCAL + (OF_P + 1024) * 4;  // 114272 -> 2 CTAs/SM

__device__ __forceinline__ uint32_t f2tf(float x) {
    uint32_t r;
    asm("cvt.rna.tf32.f32 %0, %1;" : "=r"(r) : "f"(x));
    return r;
}

__device__ __forceinline__ void mma_tf32(float* d, const uint32_t* a, uint32_t b0, uint32_t b1) {
    asm volatile(
        "mma.sync.aligned.m16n8k8.row.col.f32.tf32.tf32.f32 "
        "{%0,%1,%2,%3}, {%4,%5,%6,%7}, {%8,%9}, {%0,%1,%2,%3};"
        : "+f"(d[0]), "+f"(d[1]), "+f"(d[2]), "+f"(d[3])
        : "r"(a[0]), "r"(a[1]), "r"(a[2]), "r"(a[3]), "r"(b0), "r"(b1));
}

__global__ __launch_bounds__(256, 2)
void spil_kernel(const float* __restrict__ cxyz_g,  const float* __restrict__ cfeat_g,
                 const float* __restrict__ nxyz_g,  const float* __restrict__ nfeat_g,
                 const float* __restrict__ phi_w,   const float* __restrict__ phi_b,
                 const float* __restrict__ theta_w, const float* __restrict__ theta_b,
                 const float* __restrict__ m1_w,    const float* __restrict__ m1_b,
                 const float* __restrict__ m2_w,    const float* __restrict__ m2_b,
                 const float* __restrict__ psi_w,   const float* __restrict__ psi_b,
                 const float* __restrict__ z_w,     const float* __restrict__ z_b,
                 float* __restrict__ out)
{
    extern __shared__ __align__(16) char smem[];
    float* As = (float*)(smem + SM_A);
    float* sc = (float*)(smem + SM_SCAL);
    const int tid = threadIdx.x;
    const int wid = tid >> 5, lid = tid & 31;
    const int g = lid >> 2, tg = lid & 3;   // mma groupID / threadID_in_group
    const long g0 = (long)blockIdx.x * 4;   // first point of this tile

    // ---- stage A: nf tile 128x128 fp32, padded row-major ----
    const float4* nf4 = (const float4*)(nfeat_g + g0 * (KNN * C_));
    #pragma unroll 4
    for (int i = tid; i < 4096; i += 256) {
        float4 v = nf4[i];
        int f = i << 2;
        int r = f >> 7, c = f & 127;
        *(float4*)(As + r * SA_STR + c) = v;
    }
    // ---- stage Bp: theta^T pre-cvt to tf32, pair-packed ----
    // Bp[kc][ncol][tg] = float2( tf32(theta[kc*8+tg][ncol]), tf32(theta[kc*8+tg+4][ncol]) )
    {
        float2* Bp = (float2*)(smem + SM_B);
        #pragma unroll 4
        for (int i = tid; i < 4096; i += 256) {
            int kc = i >> 8, rest = i & 255;
            int ncol = rest >> 2, t = rest & 3;
            int k0 = kc * 8 + t;
            float v0 = theta_w[k0 * 64 + ncol];
            float v1 = theta_w[(k0 + 4) * 64 + ncol];
            float2 pk;
            pk.x = __uint_as_float(f2tf(v0));
            pk.y = __uint_as_float(f2tf(v1));
            Bp[i] = pk;
        }
    }
    // ---- small stages ----
    for (int i = tid; i < 512; i += 256) sc[OF_CF + i] = cfeat_g[g0 * C_ + i];
    for (int i = tid; i < 384; i += 256) sc[OF_NX + i] = nxyz_g[g0 * (KNN * 3) + i];
    if (tid < 12) sc[OF_CX + tid] = cxyz_g[g0 * 3 + tid];
    if (tid < 96) { sc[OF_M1W + tid] = m1_w[tid]; sc[OF_M2W + tid] = m2_w[tid]; }
    if (tid < 32) { sc[OF_M1B + tid] = m1_b[tid]; sc[OF_M2B + tid] = m2_b[tid]; }
    if (tid < 64) {
        sc[OF_PSW + tid] = psi_w[tid];  sc[OF_THB + tid] = theta_b[tid];
        sc[OF_ZB + tid]  = z_b[tid];    sc[OF_PHB + tid] = phi_b[tid];
    }
    if (tid == 0) sc[OF_PSB] = psi_b[0];
    __syncthreads();

    // ---- MMA: D[128x64] = A[128x128] @ theta[128x64], tf32. warp w = rows 16w.. ----
    float d[8][4];
    #pragma unroll
    for (int n = 0; n < 8; n++)
        #pragma unroll
        for (int j = 0; j < 4; j++) d[n][j] = 0.f;
    {
        const float* Ar0 = As + (16 * wid + g) * SA_STR;
        const float* Ar1 = Ar0 + 8 * SA_STR;
        const float2* Bp = (const float2*)(smem + SM_B);
        #pragma unroll
        for (int kc = 0; kc < 16; kc++) {
            uint32_t a[4];
            a[0] = f2tf(Ar0[kc * 8 + tg]);
            a[1] = f2tf(Ar1[kc * 8 + tg]);
            a[2] = f2tf(Ar0[kc * 8 + tg + 4]);
            a[3] = f2tf(Ar1[kc * 8 + tg + 4]);
            const float2* bk = Bp + kc * 256 + g * 4 + tg;  // + ntile*32
            #pragma unroll
            for (int n = 0; n < 8; n++) {
                float2 bv = bk[n * 32];
                mma_tf32(d[n], a, __float_as_uint(bv.x), __float_as_uint(bv.y));
            }
        }
    }
    __syncthreads();  // all warps done reading Bp

    // ---- store D over Bp region (stride 65) ----
    {
        float* Ds = (float*)(smem + SM_B);
        int r0 = 16 * wid + g, r1 = r0 + 8;
        #pragma unroll
        for (int n = 0; n < 8; n++) {
            int c0 = n * 8 + tg * 2;
            Ds[r0 * SD_STR + c0]     = d[n][0];
            Ds[r0 * SD_STR + c0 + 1] = d[n][1];
            Ds[r1 * SD_STR + c0]     = d[n][2];
            Ds[r1 * SD_STR + c0 + 1] = d[n][3];
        }
    }

    // ---- feat_i partials: thread (h, cc), each phi_w byte read once per CTA ----
    {
        int h = tid & 63, cc = tid >> 6;
        float a0 = 0.f, a1 = 0.f, a2 = 0.f, a3 = 0.f;
        int cbeg = cc * 32;
        #pragma unroll 8
        for (int c = cbeg; c < cbeg + 32; c++) {
            float f = phi_w[c * 64 + h];
            a0 = fmaf(sc[OF_CF + c], f, a0);
            a1 = fmaf(sc[OF_CF + 128 + c], f, a1);
            a2 = fmaf(sc[OF_CF + 256 + c], f, a2);
            a3 = fmaf(sc[OF_CF + 384 + c], f, a3);
        }
        sc[OF_P + (cc * 4 + 0) * 64 + h] = a0;
        sc[OF_P + (cc * 4 + 1) * 64 + h] = a1;
        sc[OF_P + (cc * 4 + 2) * 64 + h] = a2;
        sc[OF_P + (cc * 4 + 3) * 64 + h] = a3;
    }
    // ---- s_i = pos_i-half of psi ----
    if (tid < 4) {
        int p = tid;
        float x = sc[OF_CX + p * 3], y = sc[OF_CX + p * 3 + 1], z = sc[OF_CX + p * 3 + 2];
        float s = sc[OF_PSB];
        #pragma unroll
        for (int j = 0; j < 32; j++) {
            float v = sc[OF_M1B + j] + x * sc[OF_M1W + j] + y * sc[OF_M1W + 32 + j]
                    + z * sc[OF_M1W + 64 + j];
            s = fmaf(fmaxf(v, 0.f), sc[OF_PSW + j], s);
        }
        sc[OF_SI + p] = s;
    }
    __syncthreads();

    // ---- feat_i reduce ----
    {
        int p = tid >> 6, h = tid & 63;
        float v = sc[OF_P + p * 64 + h] + sc[OF_P + (4 + p) * 64 + h]
                + sc[OF_P + (8 + p) * 64 + h] + sc[OF_P + (12 + p) * 64 + h]
                + sc[OF_PHB + h];
        sc[OF_FI + p * 64 + h] = fmaxf(v, 0.f);
    }
    __syncthreads();

    // ---- epilogue: warp p = point p, lane k = neighbor; softmax over K=32 ----
    if (wid < 4) {
        const float* Ds = (const float*)(smem + SM_B);
        const int p = wid, k = lid;
        const int r = p * KNN + k;

        float rf = 0.f;
        const float* fi = &sc[OF_FI + p * 64];
        #pragma unroll
        for (int h = 0; h < H_; h++) {
            float fj = fmaxf(Ds[r * SD_STR + h] + sc[OF_THB + h], 0.f);
            rf = fmaf(fi[h], fj, rf);
        }
        rf *= 0.125f;  // 1/sqrt(H)

        const float* nx = &sc[OF_NX + r * 3];
        float px = nx[0], py = nx[1], pz = nx[2];
        float acc = sc[OF_SI + p];
        #pragma unroll
        for (int j = 0; j < 32; j++) {
            float v = sc[OF_M2B + j] + px * sc[OF_M2W + j] + py * sc[OF_M2W + 32 + j]
                    + pz * sc[OF_M2W + 64 + j];
            acc = fmaf(fmaxf(v, 0.f), sc[OF_PSW + 32 + j], acc);
        }
        float rl = fmaxf(acc, 0.f);

        float cx = sc[OF_CX + p * 3], cy = sc[OF_CX + p * 3 + 1], cz = sc[OF_CX + p * 3 + 2];
        float dx = cx - px, dy = cy - py, dz = cz - pz;
        float d2 = dx * dx + dy * dy + dz * dz;
        if (cz == pz && d2 > 0.0016f) rl = 0.f;  // same frame AND dist > 0.04

        float m = rf;
        #pragma unroll
        for (int o = 16; o; o >>= 1) m = fmaxf(m, __shfl_xor_sync(0xFFFFFFFFu, m, o));
        float e = rl * __expf(rf - m);
        float s = e;
        #pragma unroll
        for (int o = 16; o; o >>= 1) s += __shfl_xor_sync(0xFFFFFFFFu, s, o);
        float inv = 1.f / (s + 1e-8f);
        sc[OF_W + r] = e * inv;
        if (k == 0) sc[OF_SW + p] = s * inv;
    }
    __syncthreads();

    // ---- agg[p][c] = sum_k W * nf  (A reread from padded fp32 smem) ----
    #pragma unroll
    for (int it = 0; it < 2; it++) {
        int idx = tid + it * 256;
        int p = idx >> 7, c = idx & 127;
        float a = 0.f;
        const float* wp = &sc[OF_W + p * KNN];
        const float* ap = As + (p * KNN) * SA_STR + c;
        #pragma unroll 8
        for (int k = 0; k < KNN; k++) a = fmaf(wp[k], ap[k * SA_STR], a);
        sc[OF_AGG + idx] = a;
    }
    __syncthreads();

    // ---- z partials: thread (h, cc), each z_w byte read once per CTA ----
    {
        int h = tid & 63, cc = tid >> 6;
        float a0 = 0.f, a1 = 0.f, a2 = 0.f, a3 = 0.f;
        int cbeg = cc * 32;
        #pragma unroll 8
        for (int c = cbeg; c < cbeg + 32; c++) {
            float f = z_w[c * 64 + h];
            a0 = fmaf(sc[OF_AGG + c], f, a0);
            a1 = fmaf(sc[OF_AGG + 128 + c], f, a1);
            a2 = fmaf(sc[OF_AGG + 256 + c], f, a2);
            a3 = fmaf(sc[OF_AGG + 384 + c], f, a3);
        }
        sc[OF_P + (cc * 4 + 0) * 64 + h] = a0;
        sc[OF_P + (cc * 4 + 1) * 64 + h] = a1;
        sc[OF_P + (cc * 4 + 2) * 64 + h] = a2;
        sc[OF_P + (cc * 4 + 3) * 64 + h] = a3;
    }
    __syncthreads();

    // ---- z reduce + bias hoist + write ----
    {
        int p = tid >> 6, h = tid & 63;
        float v = sc[OF_P + p * 64 + h] + sc[OF_P + (4 + p) * 64 + h]
                + sc[OF_P + (8 + p) * 64 + h] + sc[OF_P + (12 + p) * 64 + h]
                + sc[OF_SW + p] * sc[OF_ZB + h];
        out[(g0 + p) * H_ + h] = v;
    }
}

extern "C" void kernel_launch(void* const* d_in, const int* in_sizes, int n_in,
                              void* d_out, int out_size) {
    (void)in_sizes; (void)n_in; (void)out_size;
    cudaFuncSetAttribute(spil_kernel, cudaFuncAttributeMaxDynamicSharedMemorySize, SMEM_BYTES);
    spil_kernel<<<8192, 256, SMEM_BYTES>>>(
        (const float*)d_in[0],  (const float*)d_in[1],
        (const float*)d_in[2],  (const float*)d_in[3],
        (const float*)d_in[4],  (const float*)d_in[5],
        (const float*)d_in[6],  (const float*)d_in[7],
        (const float*)d_in[8],  (const float*)d_in[9],
        (const float*)d_in[10], (const float*)d_in[11],
        (const float*)d_in[12], (const float*)d_in[13],
        (const float*)d_in[14], (const float*)d_in[15],
        (float*)d_out);
}

// round 6
// speedup vs baseline: 1.1642x; 1.1642x over previous
#include <cuda_runtime.h>
#include <cstdint>

// SPIL layer, fused single kernel — sm_103-safe (mma.sync tf32, no tcgen05).
// One CTA = 4 points (128 neighbor rows). 256 threads, 2 CTAs/SM.
// Warps 0-3: theta MMA, m32n64 each (warp w = point w) -> B frags reused 2x.
// Warps 4-7: phi projection concurrently (named barrier 1).
// r_f computed from MMA accumulators in registers (no D smem round-trip).

#define KNN 32
#define C_ 128
#define H_ 64

static constexpr int SA_STR = 132;               // A row stride (floats), conflict-free
static constexpr int SM_A   = 0;                 // 128 x 132 fp32(tf32-rounded) = 67584 B
static constexpr int SM_B   = 67584;             // Bp packed tf32 float2, 32768 B
static constexpr int SM_SCAL = 100352;           // scalar float region (16B aligned)
// float offsets inside scalar region
static constexpr int OF_CF  = 0;     // center_features 4x128
static constexpr int OF_NX  = 512;   // neighbor_xyz 4x32x3
static constexpr int OF_CX  = 896;   // center_xyz 4x3
static constexpr int OF_FI  = 908;   // feat_i 4x64 (relu applied)
static constexpr int OF_W   = 1164;  // W_ij 128
static constexpr int OF_SW  = 1292;  // sumW 4
static constexpr int OF_SI  = 1296;  // s_i 4
static constexpr int OF_AGG = 1300;  // agg 4x128 (16B aligned: 1300*4%16==0)
static constexpr int OF_P   = 1812;  // partials scratch (phi: 512, z: 1024)
static constexpr int OF_M1W = 2836, OF_M1B = 2932, OF_M2W = 2964, OF_M2B = 3060;
static constexpr int OF_PSW = 3092, OF_THB = 3156, OF_ZB = 3220, OF_PHB = 3284, OF_PSB = 3348;
static constexpr int SMEM_BYTES = SM_SCAL + 3352 * 4;   // 113760 -> 2 CTAs/SM

__device__ __forceinline__ uint32_t f2tf(float x) {
    uint32_t r;
    asm("cvt.rna.tf32.f32 %0, %1;" : "=r"(r) : "f"(x));
    return r;
}

__device__ __forceinline__ void mma_tf32(float* d, uint32_t a0, uint32_t a1, uint32_t a2,
                                         uint32_t a3, uint32_t b0, uint32_t b1) {
    asm volatile(
        "mma.sync.aligned.m16n8k8.row.col.f32.tf32.tf32.f32 "
        "{%0,%1,%2,%3}, {%4,%5,%6,%7}, {%8,%9}, {%0,%1,%2,%3};"
        : "+f"(d[0]), "+f"(d[1]), "+f"(d[2]), "+f"(d[3])
        : "r"(a0), "r"(a1), "r"(a2), "r"(a3), "r"(b0), "r"(b1));
}

__global__ __launch_bounds__(256, 2)
void spil_kernel(const float* __restrict__ cxyz_g,  const float* __restrict__ cfeat_g,
                 const float* __restrict__ nxyz_g,  const float* __restrict__ nfeat_g,
                 const float* __restrict__ phi_w,   const float* __restrict__ phi_b,
                 const float* __restrict__ theta_w, const float* __restrict__ theta_b,
                 const float* __restrict__ m1_w,    const float* __restrict__ m1_b,
                 const float* __restrict__ m2_w,    const float* __restrict__ m2_b,
                 const float* __restrict__ psi_w,   const float* __restrict__ psi_b,
                 const float* __restrict__ z_w,     const float* __restrict__ z_b,
                 float* __restrict__ out)
{
    extern __shared__ __align__(16) char smem[];
    float* As = (float*)(smem + SM_A);
    float* sc = (float*)(smem + SM_SCAL);
    const int tid = threadIdx.x;
    const int wid = tid >> 5, lid = tid & 31;
    const int g = lid >> 2, tg = lid & 3;   // mma groupID / threadID-in-group
    const long g0 = (long)blockIdx.x * 4;

    // ---- stage A: nf tile 128x128, pre-rounded to tf32, padded row-major ----
    const float4* nf4 = (const float4*)(nfeat_g + g0 * (KNN * C_));
    #pragma unroll 4
    for (int it = 0; it < 16; it++) {
        int i = tid + it * 256;
        float4 v = nf4[i];
        v.x = __uint_as_float(f2tf(v.x));
        v.y = __uint_as_float(f2tf(v.y));
        v.z = __uint_as_float(f2tf(v.z));
        v.w = __uint_as_float(f2tf(v.w));
        int f = i << 2;
        int r = f >> 7, c = f & 127;
        *(float4*)(As + r * SA_STR + c) = v;
    }
    // ---- stage Bp: theta^T pre-cvt tf32, pair-packed (validated round 5) ----
    {
        float2* Bp = (float2*)(smem + SM_B);
        #pragma unroll 4
        for (int it = 0; it < 16; it++) {
            int i = tid + it * 256;
            int kc = i >> 8, rest = i & 255;
            int ncol = rest >> 2, t = rest & 3;
            int k0 = kc * 8 + t;
            float2 pk;
            pk.x = __uint_as_float(f2tf(theta_w[k0 * 64 + ncol]));
            pk.y = __uint_as_float(f2tf(theta_w[(k0 + 4) * 64 + ncol]));
            Bp[i] = pk;
        }
    }
    // ---- small stages ----
    for (int i = tid; i < 512; i += 256) sc[OF_CF + i] = cfeat_g[g0 * C_ + i];
    for (int i = tid; i < 384; i += 256) sc[OF_NX + i] = nxyz_g[g0 * (KNN * 3) + i];
    if (tid < 12) sc[OF_CX + tid] = cxyz_g[g0 * 3 + tid];
    if (tid < 96) { sc[OF_M1W + tid] = m1_w[tid]; sc[OF_M2W + tid] = m2_w[tid]; }
    if (tid < 32) { sc[OF_M1B + tid] = m1_b[tid]; sc[OF_M2B + tid] = m2_b[tid]; }
    if (tid < 64) {
        sc[OF_PSW + tid] = psi_w[tid];  sc[OF_THB + tid] = theta_b[tid];
        sc[OF_ZB + tid]  = z_b[tid];    sc[OF_PHB + tid] = phi_b[tid];
    }
    if (tid == 0) sc[OF_PSB] = psi_b[0];
    __syncthreads();

    float d[2][8][4];

    if (wid < 4) {
        // ================= MMA warps: m32n64, warp w = point w =================
        #pragma unroll
        for (int mt = 0; mt < 2; mt++)
            #pragma unroll
            for (int n = 0; n < 8; n++)
                #pragma unroll
                for (int j = 0; j < 4; j++) d[mt][n][j] = 0.f;

        const float* A0 = As + (32 * wid + g) * SA_STR;        // row g
        const float* A1 = A0 + 8 * SA_STR;                     // row g+8
        const float* A2 = A0 + 16 * SA_STR;                    // row g+16
        const float* A3 = A0 + 24 * SA_STR;                    // row g+24
        const float2* Bp = (const float2*)(smem + SM_B);
        #pragma unroll
        for (int kc = 0; kc < 16; kc++) {
            const int c0 = kc * 8 + tg;
            // A already tf32-rounded in smem: raw bits ARE the tf32 operand.
            uint32_t a0 = __float_as_uint(A0[c0]),     a1 = __float_as_uint(A1[c0]);
            uint32_t a2 = __float_as_uint(A0[c0 + 4]), a3 = __float_as_uint(A1[c0 + 4]);
            uint32_t a4 = __float_as_uint(A2[c0]),     a5 = __float_as_uint(A3[c0]);
            uint32_t a6 = __float_as_uint(A2[c0 + 4]), a7 = __float_as_uint(A3[c0 + 4]);
            const float2* bk = Bp + kc * 256 + g * 4 + tg;
            #pragma unroll
            for (int n = 0; n < 8; n++) {
                float2 bv = bk[n * 32];
                uint32_t b0 = __float_as_uint(bv.x), b1 = __float_as_uint(bv.y);
                mma_tf32(d[0][n], a0, a1, a2, a3, b0, b1);   // rows g, g+8
                mma_tf32(d[1][n], a4, a5, a6, a7, b0, b1);   // rows g+16, g+24
            }
        }
    } else {
        // ================= Aux warps: phi projection + s_i =================
        const int t = tid & 127;
        const int h = t & 63, half = t >> 6;   // half = 64-col chunk
        float a0 = 0.f, a1 = 0.f, a2 = 0.f, a3 = 0.f;
        const float* cf = sc + OF_CF;
        #pragma unroll 4
        for (int cq = 0; cq < 16; cq++) {
            int c0 = half * 64 + cq * 4;
            float4 f0 = *(const float4*)&cf[c0];
            float4 f1 = *(const float4*)&cf[128 + c0];
            float4 f2 = *(const float4*)&cf[256 + c0];
            float4 f3 = *(const float4*)&cf[384 + c0];
            float w0 = phi_w[(c0 + 0) * 64 + h];
            float w1 = phi_w[(c0 + 1) * 64 + h];
            float w2 = phi_w[(c0 + 2) * 64 + h];
            float w3 = phi_w[(c0 + 3) * 64 + h];
            a0 = fmaf(f0.x, w0, fmaf(f0.y, w1, fmaf(f0.z, w2, fmaf(f0.w, w3, a0))));
            a1 = fmaf(f1.x, w0, fmaf(f1.y, w1, fmaf(f1.z, w2, fmaf(f1.w, w3, a1))));
            a2 = fmaf(f2.x, w0, fmaf(f2.y, w1, fmaf(f2.z, w2, fmaf(f2.w, w3, a2))));
            a3 = fmaf(f3.x, w0, fmaf(f3.y, w1, fmaf(f3.z, w2, fmaf(f3.w, w3, a3))));
        }
        sc[OF_P + (half * 4 + 0) * 64 + h] = a0;
        sc[OF_P + (half * 4 + 1) * 64 + h] = a1;
        sc[OF_P + (half * 4 + 2) * 64 + h] = a2;
        sc[OF_P + (half * 4 + 3) * 64 + h] = a3;
        if (t < 4) {   // s_i = pos_i half of psi
            int p = t;
            float x = sc[OF_CX + p * 3], y = sc[OF_CX + p * 3 + 1], z = sc[OF_CX + p * 3 + 2];
            float s = sc[OF_PSB];
            #pragma unroll
            for (int j = 0; j < 32; j++) {
                float v = sc[OF_M1B + j] + x * sc[OF_M1W + j] + y * sc[OF_M1W + 32 + j]
                        + z * sc[OF_M1W + 64 + j];
                s = fmaf(fmaxf(v, 0.f), sc[OF_PSW + j], s);
            }
            sc[OF_SI + p] = s;
        }
        asm volatile("bar.sync 1, 128;" ::: "memory");   // warps 4-7 only
        // FI reduce (+bias, relu): 256 items over 128 threads
        #pragma unroll
        for (int it = 0; it < 2; it++) {
            int i = t + it * 128;
            int hh = i & 63;
            float v = sc[OF_P + (i >> 6) * 64 + hh] + sc[OF_P + 256 + (i >> 6) * 64 + hh]
                    + sc[OF_PHB + hh];
            sc[OF_FI + i] = fmaxf(v, 0.f);
        }
    }
    __syncthreads();

    // ---- epilogue: warps 0-3, point p = wid; r_f from registers ----
    if (wid < 4) {
        const int p = wid;
        float rfp[4] = {0.f, 0.f, 0.f, 0.f};   // rows g, g+8, g+16, g+24 (partial over cols)
        #pragma unroll
        for (int n = 0; n < 8; n++) {
            int h0 = n * 8 + tg * 2;
            float2 tb = *(const float2*)&sc[OF_THB + h0];
            float2 fi = *(const float2*)&sc[OF_FI + p * 64 + h0];
            #pragma unroll
            for (int mt = 0; mt < 2; mt++) {
                rfp[2 * mt]     = fmaf(fi.x, fmaxf(d[mt][n][0] + tb.x, 0.f),
                                  fmaf(fi.y, fmaxf(d[mt][n][1] + tb.y, 0.f), rfp[2 * mt]));
                rfp[2 * mt + 1] = fmaf(fi.x, fmaxf(d[mt][n][2] + tb.x, 0.f),
                                  fmaf(fi.y, fmaxf(d[mt][n][3] + tb.y, 0.f), rfp[2 * mt + 1]));
            }
        }
        #pragma unroll
        for (int j = 0; j < 4; j++) {
            rfp[j] += __shfl_xor_sync(0xFFFFFFFFu, rfp[j], 1);
            rfp[j] += __shfl_xor_sync(0xFFFFFFFFu, rfp[j], 2);
        }
        // quad transpose: lane (g,tg) owns row g + 8*tg  (rfp order: g,g+8,g+16,g+24)
        float rf = rfp[tg] * 0.125f;           // 1/sqrt(H)
        const int row = g + 8 * tg;            // within-point row, permuted over lanes
        const int r = p * KNN + row;

        const float* nx = &sc[OF_NX + r * 3];
        float px = nx[0], py = nx[1], pz = nx[2];
        float acc = sc[OF_SI + p];
        #pragma unroll
        for (int j = 0; j < 32; j++) {
            float v = sc[OF_M2B + j] + px * sc[OF_M2W + j] + py * sc[OF_M2W + 32 + j]
                    + pz * sc[OF_M2W + 64 + j];
            acc = fmaf(fmaxf(v, 0.f), sc[OF_PSW + 32 + j], acc);
        }
        float rl = fmaxf(acc, 0.f);

        float cx = sc[OF_CX + p * 3], cy = sc[OF_CX + p * 3 + 1], cz = sc[OF_CX + p * 3 + 2];
        float dx = cx - px, dy = cy - py, dz = cz - pz;
        float d2 = dx * dx + dy * dy + dz * dz;
        if (cz == pz && d2 > 0.0016f) rl = 0.f;   // same frame AND dist > 0.04

        float m = rf;
        #pragma unroll
        for (int o = 16; o; o >>= 1) m = fmaxf(m, __shfl_xor_sync(0xFFFFFFFFu, m, o));
        float e = rl * __expf(rf - m);
        float s = e;
        #pragma unroll
        for (int o = 16; o; o >>= 1) s += __shfl_xor_sync(0xFFFFFFFFu, s, o);
        float inv = 1.f / (s + 1e-8f);
        sc[OF_W + r] = e * inv;
        if (row == 0) sc[OF_SW + p] = s * inv;
    }
    __syncthreads();

    // ---- agg[p][:] = sum_k W * nf : warp p, lane owns 4 channels (float4) ----
    if (wid < 4) {
        const int p = wid;
        float4 acc = make_float4(0.f, 0.f, 0.f, 0.f);
        const float* ab = As + (p * KNN) * SA_STR + 4 * lid;
        #pragma unroll 8
        for (int k = 0; k < KNN; k++) {
            float wk = sc[OF_W + p * KNN + k];
            float4 av = *(const float4*)(ab + k * SA_STR);
            acc.x = fmaf(wk, av.x, acc.x);
            acc.y = fmaf(wk, av.y, acc.y);
            acc.z = fmaf(wk, av.z, acc.z);
            acc.w = fmaf(wk, av.w, acc.w);
        }
        *(float4*)&sc[OF_AGG + p * 128 + 4 * lid] = acc;
    }
    __syncthreads();

    // ---- z partials: thread (h, cc) over 32-c chunk; z_w read once per CTA ----
    {
        const int h = tid & 63, cc = tid >> 6;
        const int cbeg = cc * 32;
        float a0 = 0.f, a1 = 0.f, a2 = 0.f, a3 = 0.f;
        const float* ag = sc + OF_AGG;
        #pragma unroll 2
        for (int cq = 0; cq < 8; cq++) {
            int c0 = cbeg + cq * 4;
            float4 f0 = *(const float4*)&ag[c0];
            float4 f1 = *(const float4*)&ag[128 + c0];
            float4 f2 = *(const float4*)&ag[256 + c0];
            float4 f3 = *(const float4*)&ag[384 + c0];
            float w0 = z_w[(c0 + 0) * 64 + h];
            float w1 = z_w[(c0 + 1) * 64 + h];
            float w2 = z_w[(c0 + 2) * 64 + h];
            float w3 = z_w[(c0 + 3) * 64 + h];
            a0 = fmaf(f0.x, w0, fmaf(f0.y, w1, fmaf(f0.z, w2, fmaf(f0.w, w3, a0))));
            a1 = fmaf(f1.x, w0, fmaf(f1.y, w1, fmaf(f1.z, w2, fmaf(f1.w, w3, a1))));
            a2 = fmaf(f2.x, w0, fmaf(f2.y, w1, fmaf(f2.z, w2, fmaf(f2.w, w3, a2))));
            a3 = fmaf(f3.x, w0, fmaf(f3.y, w1, fmaf(f3.z, w2, fmaf(f3.w, w3, a3))));
        }
        sc[OF_P + (cc * 4 + 0) * 64 + h] = a0;
        sc[OF_P + (cc * 4 + 1) * 64 + h] = a1;
        sc[OF_P + (cc * 4 + 2) * 64 + h] = a2;
        sc[OF_P + (cc * 4 + 3) * 64 + h] = a3;
    }
    __syncthreads();

    // ---- z reduce + hoisted bias + write ----
    {
        const int p = tid >> 6, h = tid & 63;
        float v = sc[OF_P + p * 64 + h] + sc[OF_P + (4 + p) * 64 + h]
                + sc[OF_P + (8 + p) * 64 + h] + sc[OF_P + (12 + p) * 64 + h]
                + sc[OF_SW + p] * sc[OF_ZB + h];
        out[(g0 + p) * H_ + h] = v;
    }
}

extern "C" void kernel_launch(void* const* d_in, const int* in_sizes, int n_in,
                              void* d_out, int out_size) {
    (void)in_sizes; (void)n_in; (void)out_size;
    cudaFuncSetAttribute(spil_kernel, cudaFuncAttributeMaxDynamicSharedMemorySize, SMEM_BYTES);
    spil_kernel<<<8192, 256, SMEM_BYTES>>>(
        (const float*)d_in[0],  (const float*)d_in[1],
        (const float*)d_in[2],  (const float*)d_in[3],
        (const float*)d_in[4],  (const float*)d_in[5],
        (const float*)d_in[6],  (const float*)d_in[7],
        (const float*)d_in[8],  (const float*)d_in[9],
        (const float*)d_in[10], (const float*)d_in[11],
        (const float*)d_in[12], (const float*)d_in[13],
        (const float*)d_in[14], (const float*)d_in[15],
        (float*)d_out);
}

// round 7
// speedup vs baseline: 1.7111x; 1.4697x over previous
#include <cuda_runtime.h>
#include <cuda_fp16.h>
#include <cstdint>

// SPIL layer, fused — sm_103-safe: mma.sync.m16n8k16.f16 (10-bit mantissa == tf32).
// One CTA = 4 points (128 neighbor rows). 256 threads, 3 CTAs/SM (63KB smem, <=80 regs).
// All 8 warps MMA (warp w = rows 16w..16w+15); theta pre-packed to fp16 frags by a
// setup kernel into __device__ global (L2-resident). A tile fp16 (serves MMA + agg).
// z projection hoisted out of K: out = (sum_k W_k nf_k) @ z_w + (sum W) z_b.

#define KNN 32
#define C_ 128
#define H_ 64

static constexpr int SAH_STR = 136;   // A stride in halves: 68 words == 4 mod 32 -> LDSM conflict-free
static constexpr int SM_A    = 0;     // 128 x 136 fp16 = 34816 B
static constexpr int SM_B    = 34816; // Bh packed fp16 frags, 1024 float4 = 16384 B
static constexpr int SM_SCAL = 51200; // scalar float region
// float offsets inside scalar region
static constexpr int OF_CF  = 0;     // center_features 4x128 (reused as AGG later)
static constexpr int OF_NX  = 512;   // neighbor_xyz 4x32x3
static constexpr int OF_CX  = 896;   // center_xyz 4x3
static constexpr int OF_FI  = 908;   // feat_i 4x64 (relu applied)
static constexpr int OF_RF  = 1164;  // r_f dot results 128
static constexpr int OF_W   = 1292;  // W_ij 128
static constexpr int OF_SW  = 1420;  // sumW 4
static constexpr int OF_SI  = 1424;  // s_i 4
static constexpr int OF_P   = 1428;  // partials scratch 16x64 (phi uses 1st half, z all)
static constexpr int OF_M1W = 2452, OF_M1B = 2548, OF_M2W = 2580, OF_M2B = 2676;
static constexpr int OF_PSW = 2708, OF_THB = 2772, OF_ZB = 2836, OF_PHB = 2900, OF_PSB = 2964;
static constexpr int SMEM_BYTES = SM_SCAL + 2968 * 4;   // 63072 B -> 3 CTAs/SM

// theta_w packed as fp16 mma B-fragments: [kc][j][lane] float4, kc=0..7, j=0..3
// float4 = { b0(n=2j), b1(n=2j), b0(n=2j+1), b1(n=2j+1) } for lane (g,tg)
__device__ float4 g_Bh[1024];

__global__ void pack_theta(const float* __restrict__ theta_w) {
    int i = blockIdx.x * blockDim.x + threadIdx.x;
    if (i >= 1024) return;
    int lane = i & 31, j = (i >> 5) & 3, kc = i >> 7;
    int g = lane >> 2, tg = lane & 3;
    int k0 = kc * 16 + 2 * tg;
    int n0 = j * 16 + g;        // n-tile 2j, col n0
    int n1 = n0 + 8;            // n-tile 2j+1
    __half2 u0 = __floats2half2_rn(theta_w[k0 * 64 + n0], theta_w[(k0 + 1) * 64 + n0]);
    __half2 u1 = __floats2half2_rn(theta_w[(k0 + 8) * 64 + n0], theta_w[(k0 + 9) * 64 + n0]);
    __half2 u2 = __floats2half2_rn(theta_w[k0 * 64 + n1], theta_w[(k0 + 1) * 64 + n1]);
    __half2 u3 = __floats2half2_rn(theta_w[(k0 + 8) * 64 + n1], theta_w[(k0 + 9) * 64 + n1]);
    float4 v;
    v.x = __uint_as_float(*(uint32_t*)&u0);
    v.y = __uint_as_float(*(uint32_t*)&u1);
    v.z = __uint_as_float(*(uint32_t*)&u2);
    v.w = __uint_as_float(*(uint32_t*)&u3);
    g_Bh[i] = v;
}

__device__ __forceinline__ uint32_t smem_u32(const void* p) {
    uint32_t a;
    asm("{ .reg .u64 t; cvta.to.shared.u64 t, %1; cvt.u32.u64 %0, t; }" : "=r"(a) : "l"(p));
    return a;
}

__device__ __forceinline__ void mma_f16(float* d, uint32_t a0, uint32_t a1, uint32_t a2,
                                        uint32_t a3, uint32_t b0, uint32_t b1) {
    asm volatile(
        "mma.sync.aligned.m16n8k16.row.col.f32.f16.f16.f32 "
        "{%0,%1,%2,%3}, {%4,%5,%6,%7}, {%8,%9}, {%0,%1,%2,%3};"
        : "+f"(d[0]), "+f"(d[1]), "+f"(d[2]), "+f"(d[3])
        : "r"(a0), "r"(a1), "r"(a2), "r"(a3), "r"(b0), "r"(b1));
}

__global__ __launch_bounds__(256, 3)
void spil_kernel(const float* __restrict__ cxyz_g,  const float* __restrict__ cfeat_g,
                 const float* __restrict__ nxyz_g,  const float* __restrict__ nfeat_g,
                 const float* __restrict__ phi_w,   const float* __restrict__ phi_b,
                 const float* __restrict__ theta_w, const float* __restrict__ theta_b,
                 const float* __restrict__ m1_w,    const float* __restrict__ m1_b,
                 const float* __restrict__ m2_w,    const float* __restrict__ m2_b,
                 const float* __restrict__ psi_w,   const float* __restrict__ psi_b,
                 const float* __restrict__ z_w,     const float* __restrict__ z_b,
                 float* __restrict__ out)
{
    extern __shared__ __align__(16) char smem[];
    float* sc = (float*)(smem + SM_SCAL);
    const uint32_t sbase = smem_u32(smem);
    const int tid = threadIdx.x;
    const int wid = tid >> 5, lid = tid & 31;
    const int g = lid >> 2, tg = lid & 3;
    const long g0 = (long)blockIdx.x * 4;

    // ---- stage A: nf 128x128 fp32 -> fp16, stride-136 row-major ----
    const float4* nf4 = (const float4*)(nfeat_g + g0 * (KNN * C_));
    #pragma unroll 4
    for (int it = 0; it < 16; it++) {
        int i = tid + it * 256;
        float4 v = nf4[i];
        int f = i << 2;
        int r = f >> 7, c = f & 127;
        __half2 h0 = __floats2half2_rn(v.x, v.y);
        __half2 h1 = __floats2half2_rn(v.z, v.w);
        uint2 uv = make_uint2(*(uint32_t*)&h0, *(uint32_t*)&h1);
        *(uint2*)(smem + SM_A + (r * SAH_STR + c) * 2) = uv;
    }
    // ---- stage Bh: copy prepacked theta frags (16KB, L2-hit) ----
    {
        float4* Bs = (float4*)(smem + SM_B);
        #pragma unroll
        for (int it = 0; it < 4; it++) Bs[tid + it * 256] = g_Bh[tid + it * 256];
    }
    // ---- small stages ----
    for (int i = tid; i < 512; i += 256) sc[OF_CF + i] = cfeat_g[g0 * C_ + i];
    for (int i = tid; i < 384; i += 256) sc[OF_NX + i] = nxyz_g[g0 * (KNN * 3) + i];
    if (tid < 12) sc[OF_CX + tid] = cxyz_g[g0 * 3 + tid];
    if (tid < 96) { sc[OF_M1W + tid] = m1_w[tid]; sc[OF_M2W + tid] = m2_w[tid]; }
    if (tid < 32) { sc[OF_M1B + tid] = m1_b[tid]; sc[OF_M2B + tid] = m2_b[tid]; }
    if (tid < 64) {
        sc[OF_PSW + tid] = psi_w[tid];  sc[OF_THB + tid] = theta_b[tid];
        sc[OF_ZB + tid]  = z_b[tid];    sc[OF_PHB + tid] = phi_b[tid];
    }
    if (tid == 0) sc[OF_PSB] = psi_b[0];
    __syncthreads();

    // ---- phi partials: thread (h, cc), phi_w read once per CTA ----
    {
        const int h = tid & 63, cc = tid >> 6;
        const int cbeg = cc * 32;
        float a0 = 0.f, a1 = 0.f, a2 = 0.f, a3 = 0.f;
        const float* cf = sc + OF_CF;
        #pragma unroll 2
        for (int cq = 0; cq < 8; cq++) {
            int c0 = cbeg + cq * 4;
            float4 f0 = *(const float4*)&cf[c0];
            float4 f1 = *(const float4*)&cf[128 + c0];
            float4 f2 = *(const float4*)&cf[256 + c0];
            float4 f3 = *(const float4*)&cf[384 + c0];
            float w0 = phi_w[(c0 + 0) * 64 + h];
            float w1 = phi_w[(c0 + 1) * 64 + h];
            float w2 = phi_w[(c0 + 2) * 64 + h];
            float w3 = phi_w[(c0 + 3) * 64 + h];
            a0 = fmaf(f0.x, w0, fmaf(f0.y, w1, fmaf(f0.z, w2, fmaf(f0.w, w3, a0))));
            a1 = fmaf(f1.x, w0, fmaf(f1.y, w1, fmaf(f1.z, w2, fmaf(f1.w, w3, a1))));
            a2 = fmaf(f2.x, w0, fmaf(f2.y, w1, fmaf(f2.z, w2, fmaf(f2.w, w3, a2))));
            a3 = fmaf(f3.x, w0, fmaf(f3.y, w1, fmaf(f3.z, w2, fmaf(f3.w, w3, a3))));
        }
        sc[OF_P + (cc * 4 + 0) * 64 + h] = a0;
        sc[OF_P + (cc * 4 + 1) * 64 + h] = a1;
        sc[OF_P + (cc * 4 + 2) * 64 + h] = a2;
        sc[OF_P + (cc * 4 + 3) * 64 + h] = a3;
    }
    if (tid < 4) {   // s_i = pos_i half of psi
        int p = tid;
        float x = sc[OF_CX + p * 3], y = sc[OF_CX + p * 3 + 1], z = sc[OF_CX + p * 3 + 2];
        float s = sc[OF_PSB];
        #pragma unroll
        for (int j = 0; j < 32; j++) {
            float v = sc[OF_M1B + j] + x * sc[OF_M1W + j] + y * sc[OF_M1W + 32 + j]
                    + z * sc[OF_M1W + 64 + j];
            s = fmaf(fmaxf(v, 0.f), sc[OF_PSW + j], s);
        }
        sc[OF_SI + p] = s;
    }
    __syncthreads();

    // ---- FI reduce (+bias, relu) ----
    {
        const int p = tid >> 6, h = tid & 63;
        float v = sc[OF_P + p * 64 + h] + sc[OF_P + (4 + p) * 64 + h]
                + sc[OF_P + (8 + p) * 64 + h] + sc[OF_P + (12 + p) * 64 + h]
                + sc[OF_PHB + h];
        sc[OF_FI + tid] = fmaxf(v, 0.f);
    }
    __syncthreads();

    // ---- MMA: all 8 warps, warp w = rows 16w..16w+15 (m16n64k128) ----
    float dacc[8][4];
    #pragma unroll
    for (int n = 0; n < 8; n++)
        #pragma unroll
        for (int j = 0; j < 4; j++) dacc[n][j] = 0.f;
    {
        const uint32_t a_addr = sbase + SM_A
            + (uint32_t)(((16 * wid + (lid & 15)) * SAH_STR + ((lid >> 4) * 8)) * 2);
        const float4* Bs = (const float4*)(smem + SM_B);
        #pragma unroll
        for (int kc = 0; kc < 8; kc++) {
            uint32_t a0, a1, a2, a3;
            asm volatile("ldmatrix.sync.aligned.m8n8.x4.shared.b16 {%0,%1,%2,%3}, [%4];"
                         : "=r"(a0), "=r"(a1), "=r"(a2), "=r"(a3)
                         : "r"(a_addr + (uint32_t)(kc * 32)));
            #pragma unroll
            for (int j = 0; j < 4; j++) {
                float4 bv = Bs[kc * 128 + j * 32 + lid];
                mma_f16(dacc[2 * j], a0, a1, a2, a3,
                        __float_as_uint(bv.x), __float_as_uint(bv.y));
                mma_f16(dacc[2 * j + 1], a0, a1, a2, a3,
                        __float_as_uint(bv.z), __float_as_uint(bv.w));
            }
        }
    }

    // ---- r_f from accumulators: dot with FI, quad-reduce, store 16 per warp ----
    {
        const int p = wid >> 1;
        float rf0 = 0.f, rf1 = 0.f;
        #pragma unroll
        for (int n = 0; n < 8; n++) {
            int h0 = n * 8 + 2 * tg;
            float2 tb = *(const float2*)&sc[OF_THB + h0];
            float2 fi = *(const float2*)&sc[OF_FI + p * 64 + h0];
            rf0 = fmaf(fi.x, fmaxf(dacc[n][0] + tb.x, 0.f),
                  fmaf(fi.y, fmaxf(dacc[n][1] + tb.y, 0.f), rf0));
            rf1 = fmaf(fi.x, fmaxf(dacc[n][2] + tb.x, 0.f),
                  fmaf(fi.y, fmaxf(dacc[n][3] + tb.y, 0.f), rf1));
        }
        rf0 += __shfl_xor_sync(0xFFFFFFFFu, rf0, 1);
        rf0 += __shfl_xor_sync(0xFFFFFFFFu, rf0, 2);
        rf1 += __shfl_xor_sync(0xFFFFFFFFu, rf1, 1);
        rf1 += __shfl_xor_sync(0xFFFFFFFFu, rf1, 2);
        if (tg == 0) {
            sc[OF_RF + wid * 16 + g] = rf0;
            sc[OF_RF + wid * 16 + 8 + g] = rf1;
        }
    }
    __syncthreads();

    // ---- softmax: warp p, lane k = neighbor k ----
    if (wid < 4) {
        const int p = wid, k = lid, r = p * KNN + k;
        float rf = sc[OF_RF + p * 32 + k] * 0.125f;   // 1/sqrt(H)

        const float* nx = &sc[OF_NX + r * 3];
        float px = nx[0], py = nx[1], pz = nx[2];
        float acc = sc[OF_SI + p];
        #pragma unroll
        for (int j = 0; j < 32; j++) {
            float v = sc[OF_M2B + j] + px * sc[OF_M2W + j] + py * sc[OF_M2W + 32 + j]
                    + pz * sc[OF_M2W + 64 + j];
            acc = fmaf(fmaxf(v, 0.f), sc[OF_PSW + 32 + j], acc);
        }
        float rl = fmaxf(acc, 0.f);

        float cx = sc[OF_CX + p * 3], cy = sc[OF_CX + p * 3 + 1], cz = sc[OF_CX + p * 3 + 2];
        float dx = cx - px, dy = cy - py, dz = cz - pz;
        float d2 = dx * dx + dy * dy + dz * dz;
        if (cz == pz && d2 > 0.0016f) rl = 0.f;   // same frame AND dist > 0.04

        float m = rf;
        #pragma unroll
        for (int o = 16; o; o >>= 1) m = fmaxf(m, __shfl_xor_sync(0xFFFFFFFFu, m, o));
        float e = rl * __expf(rf - m);
        float s = e;
        #pragma unroll
        for (int o = 16; o; o >>= 1) s += __shfl_xor_sync(0xFFFFFFFFu, s, o);
        float inv = 1.f / (s + 1e-8f);
        sc[OF_W + r] = e * inv;
        if (k == 0) sc[OF_SW + p] = s * inv;
    }
    __syncthreads();

    // ---- agg: all 8 warps; warp w -> point w>>1, col-half w&1; lane = 2 cols ----
    {
        const int p = wid >> 1;
        const int c0 = (wid & 1) * 64 + 2 * lid;
        const float* wp = &sc[OF_W + p * KNN];
        const char* ab = smem + SM_A + c0 * 2;
        float ax = 0.f, ay = 0.f;
        #pragma unroll 8
        for (int k = 0; k < KNN; k++) {
            float wk = wp[k];
            __half2 hv = *(const __half2*)(ab + (p * KNN + k) * (SAH_STR * 2));
            float2 fv = __half22float2(hv);
            ax = fmaf(wk, fv.x, ax);
            ay = fmaf(wk, fv.y, ay);
        }
        sc[OF_CF + p * 128 + c0]     = ax;   // AGG overlays CF (phi done)
        sc[OF_CF + p * 128 + c0 + 1] = ay;
    }
    __syncthreads();

    // ---- z partials: thread (h, cc); z_w read once per CTA ----
    {
        const int h = tid & 63, cc = tid >> 6;
        const int cbeg = cc * 32;
        float a0 = 0.f, a1 = 0.f, a2 = 0.f, a3 = 0.f;
        const float* ag = sc + OF_CF;
        #pragma unroll 2
        for (int cq = 0; cq < 8; cq++) {
            int c0 = cbeg + cq * 4;
            float4 f0 = *(const float4*)&ag[c0];
            float4 f1 = *(const float4*)&ag[128 + c0];
            float4 f2 = *(const float4*)&ag[256 + c0];
            float4 f3 = *(const float4*)&ag[384 + c0];
            float w0 = z_w[(c0 + 0) * 64 + h];
            float w1 = z_w[(c0 + 1) * 64 + h];
            float w2 = z_w[(c0 + 2) * 64 + h];
            float w3 = z_w[(c0 + 3) * 64 + h];
            a0 = fmaf(f0.x, w0, fmaf(f0.y, w1, fmaf(f0.z, w2, fmaf(f0.w, w3, a0))));
            a1 = fmaf(f1.x, w0, fmaf(f1.y, w1, fmaf(f1.z, w2, fmaf(f1.w, w3, a1))));
            a2 = fmaf(f2.x, w0, fmaf(f2.y, w1, fmaf(f2.z, w2, fmaf(f2.w, w3, a2))));
            a3 = fmaf(f3.x, w0, fmaf(f3.y, w1, fmaf(f3.z, w2, fmaf(f3.w, w3, a3))));
        }
        sc[OF_P + (cc * 4 + 0) * 64 + h] = a0;
        sc[OF_P + (cc * 4 + 1) * 64 + h] = a1;
        sc[OF_P + (cc * 4 + 2) * 64 + h] = a2;
        sc[OF_P + (cc * 4 + 3) * 64 + h] = a3;
    }
    __syncthreads();

    // ---- z reduce + hoisted bias + write ----
    {
        const int p = tid >> 6, h = tid & 63;
        float v = sc[OF_P + p * 64 + h] + sc[OF_P + (4 + p) * 64 + h]
                + sc[OF_P + (8 + p) * 64 + h] + sc[OF_P + (12 + p) * 64 + h]
                + sc[OF_SW + p] * sc[OF_ZB + h];
        out[(g0 + p) * H_ + h] = v;
    }
}

extern "C" void kernel_launch(void* const* d_in, const int* in_sizes, int n_in,
                              void* d_out, int out_size) {
    (void)in_sizes; (void)n_in; (void)out_size;
    cudaFuncSetAttribute(spil_kernel, cudaFuncAttributeMaxDynamicSharedMemorySize, SMEM_BYTES);
    pack_theta<<<4, 256>>>((const float*)d_in[6]);
    spil_kernel<<<8192, 256, SMEM_BYTES>>>(
        (const float*)d_in[0],  (const float*)d_in[1],
        (const float*)d_in[2],  (const float*)d_in[3],
        (const float*)d_in[4],  (const float*)d_in[5],
        (const float*)d_in[6],  (const float*)d_in[7],
        (const float*)d_in[8],  (const float*)d_in[9],
        (const float*)d_in[10], (const float*)d_in[11],
        (const float*)d_in[12], (const float*)d_in[13],
        (const float*)d_in[14], (const float*)d_in[15],
        (float*)d_out);
}

// round 8
// speedup vs baseline: 1.7400x; 1.0169x over previous
#include <cuda_runtime.h>
#include <cuda_fp16.h>
#include <cstdint>

// SPIL layer, fused — sm_103-safe: mma.sync.m16n8k16.f16.
// One CTA = 4 points (128 neighbor rows). 256 threads, 4 CTAs/SM (~46KB smem, 64 regs).
// MMA: m32n32 per warp (warp w -> point w>>1, n-half w&1); B frags read from L2-resident
// prepacked __device__ global (no smem copy). Prologue (A-stage, phi, s_i) fused into one
// phase reading from global; r_l computed per-neighbor pre-softmax. z proj hoisted out of K.

#define KNN 32
#define C_ 128
#define H_ 64

static constexpr int SAH_STR = 136;   // A stride in halves; 68 words -> LDSM conflict-free
static constexpr int SM_A    = 0;     // 128 x 136 fp16 = 34816 B
static constexpr int SM_SCAL = 34816; // scalar float region
// float offsets inside scalar region
static constexpr int OF_FI  = 0;     // feat_i 4x64 (relu applied)
static constexpr int OF_RFP = 256;   // rf partials per warp [8][32]
static constexpr int OF_RL  = 512;   // r_l (masked) 128
static constexpr int OF_W   = 640;   // W_ij 128
static constexpr int OF_SW  = 768;   // sumW 4
static constexpr int OF_SI  = 772;   // s_i 4
static constexpr int OF_P   = 776;   // partials 16x64 (phi then z); 776*4%16==0
static constexpr int OF_AGP = 1800;  // agg k-half partials 8x128; 1800*4%16==0
static constexpr int SMEM_BYTES = SM_SCAL + 2824 * 4;   // 46112 B -> 4 CTAs/SM

// theta_w packed as fp16 mma B-fragments: [kc][j][lane] float4, kc=0..7, j=0..3
// float4 = { b0(n-tile 2j), b1(2j), b0(2j+1), b1(2j+1) } for lane (g,tg)
__device__ float4 g_Bh[1024];

__global__ void pack_theta(const float* __restrict__ theta_w) {
    int i = blockIdx.x * blockDim.x + threadIdx.x;
    if (i >= 1024) return;
    int lane = i & 31, j = (i >> 5) & 3, kc = i >> 7;
    int g = lane >> 2, tg = lane & 3;
    int k0 = kc * 16 + 2 * tg;
    int n0 = j * 16 + g;
    int n1 = n0 + 8;
    __half2 u0 = __floats2half2_rn(theta_w[k0 * 64 + n0], theta_w[(k0 + 1) * 64 + n0]);
    __half2 u1 = __floats2half2_rn(theta_w[(k0 + 8) * 64 + n0], theta_w[(k0 + 9) * 64 + n0]);
    __half2 u2 = __floats2half2_rn(theta_w[k0 * 64 + n1], theta_w[(k0 + 1) * 64 + n1]);
    __half2 u3 = __floats2half2_rn(theta_w[(k0 + 8) * 64 + n1], theta_w[(k0 + 9) * 64 + n1]);
    float4 v;
    v.x = __uint_as_float(*(uint32_t*)&u0);
    v.y = __uint_as_float(*(uint32_t*)&u1);
    v.z = __uint_as_float(*(uint32_t*)&u2);
    v.w = __uint_as_float(*(uint32_t*)&u3);
    g_Bh[i] = v;
}

__device__ __forceinline__ uint32_t smem_u32(const void* p) {
    uint32_t a;
    asm("{ .reg .u64 t; cvta.to.shared.u64 t, %1; cvt.u32.u64 %0, t; }" : "=r"(a) : "l"(p));
    return a;
}

__device__ __forceinline__ void mma_f16(float* d, uint32_t a0, uint32_t a1, uint32_t a2,
                                        uint32_t a3, uint32_t b0, uint32_t b1) {
    asm volatile(
        "mma.sync.aligned.m16n8k16.row.col.f32.f16.f16.f32 "
        "{%0,%1,%2,%3}, {%4,%5,%6,%7}, {%8,%9}, {%0,%1,%2,%3};"
        : "+f"(d[0]), "+f"(d[1]), "+f"(d[2]), "+f"(d[3])
        : "r"(a0), "r"(a1), "r"(a2), "r"(a3), "r"(b0), "r"(b1));
}

__global__ __launch_bounds__(256, 4)
void spil_kernel(const float* __restrict__ cxyz_g,  const float* __restrict__ cfeat_g,
                 const float* __restrict__ nxyz_g,  const float* __restrict__ nfeat_g,
                 const float* __restrict__ phi_w,   const float* __restrict__ phi_b,
                 const float* __restrict__ theta_w, const float* __restrict__ theta_b,
                 const float* __restrict__ m1_w,    const float* __restrict__ m1_b,
                 const float* __restrict__ m2_w,    const float* __restrict__ m2_b,
                 const float* __restrict__ psi_w,   const float* __restrict__ psi_b,
                 const float* __restrict__ z_w,     const float* __restrict__ z_b,
                 float* __restrict__ out)
{
    extern __shared__ __align__(16) char smem[];
    float* sc = (float*)(smem + SM_SCAL);
    const uint32_t sbase = smem_u32(smem);
    const int tid = threadIdx.x;
    const int wid = tid >> 5, lid = tid & 31;
    const int g = lid >> 2, tg = lid & 3;
    const long g0 = (long)blockIdx.x * 4;

    // ================= P1: stage A + phi partials + s_i (all from global) =========
    // A: nf 128x128 fp32 -> fp16, stride-136 row-major
    const float4* nf4 = (const float4*)(nfeat_g + g0 * (KNN * C_));
    #pragma unroll 4
    for (int it = 0; it < 16; it++) {
        int i = tid + it * 256;
        float4 v = nf4[i];
        int f = i << 2;
        int r = f >> 7, c = f & 127;
        __half2 h0 = __floats2half2_rn(v.x, v.y);
        __half2 h1 = __floats2half2_rn(v.z, v.w);
        uint2 uv = make_uint2(*(uint32_t*)&h0, *(uint32_t*)&h1);
        *(uint2*)(smem + SM_A + (r * SAH_STR + c) * 2) = uv;
    }
    // s_i from global (tid<4)
    if (tid < 4) {
        float x = cxyz_g[(g0 + tid) * 3], y = cxyz_g[(g0 + tid) * 3 + 1],
              z = cxyz_g[(g0 + tid) * 3 + 2];
        float s = psi_b[0];
        #pragma unroll 8
        for (int j = 0; j < 32; j++) {
            float v = m1_b[j] + x * m1_w[j] + y * m1_w[32 + j] + z * m1_w[64 + j];
            s = fmaf(fmaxf(v, 0.f), psi_w[j], s);
        }
        sc[OF_SI + tid] = s;
    }
    // phi partials: thread (h, cc); cf via broadcast LDG, phi_w coalesced, read once/CTA
    {
        const int h = tid & 63, cc = tid >> 6;
        const int cbeg = cc * 32;
        float a0 = 0.f, a1 = 0.f, a2 = 0.f, a3 = 0.f;
        const float* cf = cfeat_g + g0 * C_;
        #pragma unroll 2
        for (int cq = 0; cq < 8; cq++) {
            int c0 = cbeg + cq * 4;
            float4 f0 = *(const float4*)&cf[c0];
            float4 f1 = *(const float4*)&cf[128 + c0];
            float4 f2 = *(const float4*)&cf[256 + c0];
            float4 f3 = *(const float4*)&cf[384 + c0];
            float w0 = phi_w[(c0 + 0) * 64 + h];
            float w1 = phi_w[(c0 + 1) * 64 + h];
            float w2 = phi_w[(c0 + 2) * 64 + h];
            float w3 = phi_w[(c0 + 3) * 64 + h];
            a0 = fmaf(f0.x, w0, fmaf(f0.y, w1, fmaf(f0.z, w2, fmaf(f0.w, w3, a0))));
            a1 = fmaf(f1.x, w0, fmaf(f1.y, w1, fmaf(f1.z, w2, fmaf(f1.w, w3, a1))));
            a2 = fmaf(f2.x, w0, fmaf(f2.y, w1, fmaf(f2.z, w2, fmaf(f2.w, w3, a2))));
            a3 = fmaf(f3.x, w0, fmaf(f3.y, w1, fmaf(f3.z, w2, fmaf(f3.w, w3, a3))));
        }
        sc[OF_P + (cc * 4 + 0) * 64 + h] = a0;
        sc[OF_P + (cc * 4 + 1) * 64 + h] = a1;
        sc[OF_P + (cc * 4 + 2) * 64 + h] = a2;
        sc[OF_P + (cc * 4 + 3) * 64 + h] = a3;
    }
    __syncthreads();

    // ================= P2: r_l (tid<128) || FI reduce (tid>=128) ==================
    if (tid < 128) {
        const int r = tid, pp = r >> 5;
        float nx = nxyz_g[g0 * 96 + r * 3], ny = nxyz_g[g0 * 96 + r * 3 + 1],
              nz = nxyz_g[g0 * 96 + r * 3 + 2];
        float cx = cxyz_g[(g0 + pp) * 3], cy = cxyz_g[(g0 + pp) * 3 + 1],
              cz = cxyz_g[(g0 + pp) * 3 + 2];
        float acc = sc[OF_SI + pp];
        #pragma unroll 8
        for (int j = 0; j < 32; j++) {
            float v = m2_b[j] + nx * m2_w[j] + ny * m2_w[32 + j] + nz * m2_w[64 + j];
            acc = fmaf(fmaxf(v, 0.f), psi_w[32 + j], acc);
        }
        float rl = fmaxf(acc, 0.f);
        float dx = cx - nx, dy = cy - ny, dz = cz - nz;
        if (cz == nz && dx * dx + dy * dy + dz * dz > 0.0016f) rl = 0.f;  // SPIL mask
        sc[OF_RL + r] = rl;
    } else {
        #pragma unroll
        for (int e = 0; e < 2; e++) {
            int i = (tid - 128) * 2 + e;
            int pp = i >> 6, h = i & 63;
            float v = sc[OF_P + pp * 64 + h] + sc[OF_P + (4 + pp) * 64 + h]
                    + sc[OF_P + (8 + pp) * 64 + h] + sc[OF_P + (12 + pp) * 64 + h]
                    + phi_b[h];
            sc[OF_FI + i] = fmaxf(v, 0.f);
        }
    }
    __syncthreads();

    // ================= P3: MMA m32n32 (warp w: point w>>1, n-half w&1) ============
    const int p = wid >> 1, nh = wid & 1;
    float dacc[2][4][4];   // [m-tile][n8-tile][frag]
    #pragma unroll
    for (int mt = 0; mt < 2; mt++)
        #pragma unroll
        for (int t = 0; t < 4; t++)
            #pragma unroll
            for (int j = 0; j < 4; j++) dacc[mt][t][j] = 0.f;
    {
        const uint32_t aa0 = sbase + SM_A
            + (uint32_t)(((p * 32 + (lid & 15)) * SAH_STR + ((lid >> 4) * 8)) * 2);
        const uint32_t aa1 = aa0 + (uint32_t)(16 * SAH_STR * 2);
        #pragma unroll
        for (int kc = 0; kc < 8; kc++) {
            uint32_t x0, x1, x2, x3, y0, y1, y2, y3;
            asm volatile("ldmatrix.sync.aligned.m8n8.x4.shared.b16 {%0,%1,%2,%3}, [%4];"
                         : "=r"(x0), "=r"(x1), "=r"(x2), "=r"(x3)
                         : "r"(aa0 + (uint32_t)(kc * 32)));
            asm volatile("ldmatrix.sync.aligned.m8n8.x4.shared.b16 {%0,%1,%2,%3}, [%4];"
                         : "=r"(y0), "=r"(y1), "=r"(y2), "=r"(y3)
                         : "r"(aa1 + (uint32_t)(kc * 32)));
            float4 bv0 = __ldg(&g_Bh[kc * 128 + (2 * nh) * 32 + lid]);
            float4 bv1 = __ldg(&g_Bh[kc * 128 + (2 * nh + 1) * 32 + lid]);
            uint32_t b0 = __float_as_uint(bv0.x), b1 = __float_as_uint(bv0.y);
            uint32_t b2 = __float_as_uint(bv0.z), b3 = __float_as_uint(bv0.w);
            uint32_t b4 = __float_as_uint(bv1.x), b5 = __float_as_uint(bv1.y);
            uint32_t b6 = __float_as_uint(bv1.z), b7 = __float_as_uint(bv1.w);
            mma_f16(dacc[0][0], x0, x1, x2, x3, b0, b1);
            mma_f16(dacc[0][1], x0, x1, x2, x3, b2, b3);
            mma_f16(dacc[0][2], x0, x1, x2, x3, b4, b5);
            mma_f16(dacc[0][3], x0, x1, x2, x3, b6, b7);
            mma_f16(dacc[1][0], y0, y1, y2, y3, b0, b1);
            mma_f16(dacc[1][1], y0, y1, y2, y3, b2, b3);
            mma_f16(dacc[1][2], y0, y1, y2, y3, b4, b5);
            mma_f16(dacc[1][3], y0, y1, y2, y3, b6, b7);
        }
    }
    // rf partials: dot with FI over this warp's 32 h-cols, quad-reduce + transpose
    {
        float rfp[4] = {0.f, 0.f, 0.f, 0.f};   // rows g, g+8, g+16, g+24
        #pragma unroll
        for (int t = 0; t < 4; t++) {
            int h0 = nh * 32 + t * 8 + 2 * tg;
            float2 fi = *(const float2*)&sc[OF_FI + p * 64 + h0];
            float2 tb = *(const float2*)&theta_b[h0];
            rfp[0] = fmaf(fi.x, fmaxf(dacc[0][t][0] + tb.x, 0.f),
                     fmaf(fi.y, fmaxf(dacc[0][t][1] + tb.y, 0.f), rfp[0]));
            rfp[1] = fmaf(fi.x, fmaxf(dacc[0][t][2] + tb.x, 0.f),
                     fmaf(fi.y, fmaxf(dacc[0][t][3] + tb.y, 0.f), rfp[1]));
            rfp[2] = fmaf(fi.x, fmaxf(dacc[1][t][0] + tb.x, 0.f),
                     fmaf(fi.y, fmaxf(dacc[1][t][1] + tb.y, 0.f), rfp[2]));
            rfp[3] = fmaf(fi.x, fmaxf(dacc[1][t][2] + tb.x, 0.f),
                     fmaf(fi.y, fmaxf(dacc[1][t][3] + tb.y, 0.f), rfp[3]));
        }
        #pragma unroll
        for (int j = 0; j < 4; j++) {
            rfp[j] += __shfl_xor_sync(0xFFFFFFFFu, rfp[j], 1);
            rfp[j] += __shfl_xor_sync(0xFFFFFFFFu, rfp[j], 2);
        }
        sc[OF_RFP + wid * 32 + g + 8 * tg] = rfp[tg];   // lane owns row g+8*tg
    }
    __syncthreads();

    // ================= P4: softmax (warps 0-3; warp p, lane k) ====================
    if (wid < 4) {
        const int k = lid, r = wid * KNN + k;
        float rf = (sc[OF_RFP + (2 * wid) * 32 + k] + sc[OF_RFP + (2 * wid + 1) * 32 + k])
                 * 0.125f;   // 1/sqrt(H)
        float rl = sc[OF_RL + r];
        float m = rf;
        #pragma unroll
        for (int o = 16; o; o >>= 1) m = fmaxf(m, __shfl_xor_sync(0xFFFFFFFFu, m, o));
        float e = rl * __expf(rf - m);
        float s = e;
        #pragma unroll
        for (int o = 16; o; o >>= 1) s += __shfl_xor_sync(0xFFFFFFFFu, s, o);
        float inv = 1.f / (s + 1e-8f);
        sc[OF_W + r] = e * inv;
        if (k == 0) sc[OF_SW + wid] = s * inv;
    }
    __syncthreads();

    // ================= P5: agg k-half partials (warp w: point w>>1, k-half w&1) ===
    {
        const int kh = wid & 1;
        const int c0 = 4 * lid;
        const char* ab = smem + SM_A + ((p * 32 + kh * 16) * SAH_STR + c0) * 2;
        float4 acc = make_float4(0.f, 0.f, 0.f, 0.f);
        #pragma unroll 8
        for (int k = 0; k < 16; k++) {
            float wk = sc[OF_W + p * KNN + kh * 16 + k];
            uint2 uv = *(const uint2*)(ab + k * (SAH_STR * 2));
            float2 f0 = __half22float2(*(__half2*)&uv.x);
            float2 f1 = __half22float2(*(__half2*)&uv.y);
            acc.x = fmaf(wk, f0.x, acc.x);
            acc.y = fmaf(wk, f0.y, acc.y);
            acc.z = fmaf(wk, f1.x, acc.z);
            acc.w = fmaf(wk, f1.y, acc.w);
        }
        *(float4*)&sc[OF_AGP + (p * 2 + kh) * 128 + c0] = acc;
    }
    __syncthreads();

    // ================= P6: z partials (thread (h,cc); z_w read once/CTA) ==========
    {
        const int h = tid & 63, cc = tid >> 6;
        const int cbeg = cc * 32;
        float a0 = 0.f, a1 = 0.f, a2 = 0.f, a3 = 0.f;
        const float* ag = sc + OF_AGP;
        #pragma unroll 2
        for (int cq = 0; cq < 8; cq++) {
            int c0 = cbeg + cq * 4;
            float4 u0a = *(const float4*)&ag[c0],       u0b = *(const float4*)&ag[128 + c0];
            float4 u1a = *(const float4*)&ag[256 + c0], u1b = *(const float4*)&ag[384 + c0];
            float4 u2a = *(const float4*)&ag[512 + c0], u2b = *(const float4*)&ag[640 + c0];
            float4 u3a = *(const float4*)&ag[768 + c0], u3b = *(const float4*)&ag[896 + c0];
            float w0 = z_w[(c0 + 0) * 64 + h];
            float w1 = z_w[(c0 + 1) * 64 + h];
            float w2 = z_w[(c0 + 2) * 64 + h];
            float w3 = z_w[(c0 + 3) * 64 + h];
            a0 = fmaf(u0a.x + u0b.x, w0, fmaf(u0a.y + u0b.y, w1,
                 fmaf(u0a.z + u0b.z, w2, fmaf(u0a.w + u0b.w, w3, a0))));
            a1 = fmaf(u1a.x + u1b.x, w0, fmaf(u1a.y + u1b.y, w1,
                 fmaf(u1a.z + u1b.z, w2, fmaf(u1a.w + u1b.w, w3, a1))));
            a2 = fmaf(u2a.x + u2b.x, w0, fmaf(u2a.y + u2b.y, w1,
                 fmaf(u2a.z + u2b.z, w2, fmaf(u2a.w + u2b.w, w3, a2))));
            a3 = fmaf(u3a.x + u3b.x, w0, fmaf(u3a.y + u3b.y, w1,
                 fmaf(u3a.z + u3b.z, w2, fmaf(u3a.w + u3b.w, w3, a3))));
        }
        sc[OF_P + (cc * 4 + 0) * 64 + h] = a0;
        sc[OF_P + (cc * 4 + 1) * 64 + h] = a1;
        sc[OF_P + (cc * 4 + 2) * 64 + h] = a2;
        sc[OF_P + (cc * 4 + 3) * 64 + h] = a3;
    }
    __syncthreads();

    // ================= P7: z reduce + hoisted bias + write ========================
    {
        const int pp = tid >> 6, h = tid & 63;
        float v = sc[OF_P + pp * 64 + h] + sc[OF_P + (4 + pp) * 64 + h]
                + sc[OF_P + (8 + pp) * 64 + h] + sc[OF_P + (12 + pp) * 64 + h]
                + sc[OF_SW + pp] * z_b[h];
        out[(g0 + pp) * H_ + h] = v;
    }
}

extern "C" void kernel_launch(void* const* d_in, const int* in_sizes, int n_in,
                              void* d_out, int out_size) {
    (void)in_sizes; (void)n_in; (void)out_size;
    cudaFuncSetAttribute(spil_kernel, cudaFuncAttributeMaxDynamicSharedMemorySize, SMEM_BYTES);
    pack_theta<<<4, 256>>>((const float*)d_in[6]);
    spil_kernel<<<8192, 256, SMEM_BYTES>>>(
        (const float*)d_in[0],  (const float*)d_in[1],
        (const float*)d_in[2],  (const float*)d_in[3],
        (const float*)d_in[4],  (const float*)d_in[5],
        (const float*)d_in[6],  (const float*)d_in[7],
        (const float*)d_in[8],  (const float*)d_in[9],
        (const float*)d_in[10], (const float*)d_in[11],
        (const float*)d_in[12], (const float*)d_in[13],
        (const float*)d_in[14], (const float*)d_in[15],
        (float*)d_out);
}

// round 9
// speedup vs baseline: 2.0139x; 1.1575x over previous
#include <cuda_runtime.h>
#include <cuda_fp16.h>
#include <cstdint>

// SPIL layer, fused — sm_103-safe: mma.sync.m16n8k16.f16.
// One CTA = 4 points (128 neighbor rows). 256 threads, 4 CTAs/SM (~47KB smem, ~64 regs).
// MMA m32n32/warp; B frags from L2-resident prepacked global. Lane-uniform MLP weights
// in __constant__ (uniform port, off l1tex). agg partials combined+transposed so the
// z inner loop does one broadcast per channel. z proj hoisted out of K.

#define KNN 32
#define C_ 128
#define H_ 64

static constexpr int SAH_STR = 136;   // A stride in halves; LDSM conflict-free
static constexpr int SM_A    = 0;     // 128 x 136 fp16 = 34816 B
static constexpr int SM_SCAL = 34816; // scalar float region
// float offsets inside scalar region
static constexpr int OF_FI  = 0;     // feat_i 4x64
static constexpr int OF_RFP = 256;   // rf partials per warp [8][32]
static constexpr int OF_RL  = 512;   // r_l (masked) 128
static constexpr int OF_W   = 640;   // W_ij 128
static constexpr int OF_SW  = 768;   // sumW 4
static constexpr int OF_SI  = 772;   // s_i 4
static constexpr int OF_P   = 776;   // partials 16x64 (phi then z)
static constexpr int OF_AGP = 1800;  // agg k-half partials 8x128
static constexpr int OF_AGT = 2824;  // agg combined transposed [128]x4 (float4/c)
static constexpr int SMEM_BYTES = SM_SCAL + 3336 * 4;   // 48160 B -> 4 CTAs/SM

// lane-uniform weights -> constant bank (uniform datapath, not l1tex)
__constant__ float C_M1W[96];
__constant__ float C_M1B[32];
__constant__ float C_M2W[96];
__constant__ float C_M2B[32];
__constant__ float C_PSW[64];
__constant__ float C_PSB[1];

// theta_w packed as fp16 mma B-fragments: [kc][j][lane] float4, kc=0..7, j=0..3
__device__ float4 g_Bh[1024];

__global__ void pack_theta(const float* __restrict__ theta_w) {
    int i = blockIdx.x * blockDim.x + threadIdx.x;
    if (i >= 1024) return;
    int lane = i & 31, j = (i >> 5) & 3, kc = i >> 7;
    int g = lane >> 2, tg = lane & 3;
    int k0 = kc * 16 + 2 * tg;
    int n0 = j * 16 + g;
    int n1 = n0 + 8;
    __half2 u0 = __floats2half2_rn(theta_w[k0 * 64 + n0], theta_w[(k0 + 1) * 64 + n0]);
    __half2 u1 = __floats2half2_rn(theta_w[(k0 + 8) * 64 + n0], theta_w[(k0 + 9) * 64 + n0]);
    __half2 u2 = __floats2half2_rn(theta_w[k0 * 64 + n1], theta_w[(k0 + 1) * 64 + n1]);
    __half2 u3 = __floats2half2_rn(theta_w[(k0 + 8) * 64 + n1], theta_w[(k0 + 9) * 64 + n1]);
    float4 v;
    v.x = __uint_as_float(*(uint32_t*)&u0);
    v.y = __uint_as_float(*(uint32_t*)&u1);
    v.z = __uint_as_float(*(uint32_t*)&u2);
    v.w = __uint_as_float(*(uint32_t*)&u3);
    g_Bh[i] = v;
}

__device__ __forceinline__ uint32_t smem_u32(const void* p) {
    uint32_t a;
    asm("{ .reg .u64 t; cvta.to.shared.u64 t, %1; cvt.u32.u64 %0, t; }" : "=r"(a) : "l"(p));
    return a;
}

__device__ __forceinline__ void mma_f16(float* d, uint32_t a0, uint32_t a1, uint32_t a2,
                                        uint32_t a3, uint32_t b0, uint32_t b1) {
    asm volatile(
        "mma.sync.aligned.m16n8k16.row.col.f32.f16.f16.f32 "
        "{%0,%1,%2,%3}, {%4,%5,%6,%7}, {%8,%9}, {%0,%1,%2,%3};"
        : "+f"(d[0]), "+f"(d[1]), "+f"(d[2]), "+f"(d[3])
        : "r"(a0), "r"(a1), "r"(a2), "r"(a3), "r"(b0), "r"(b1));
}

__global__ __launch_bounds__(256, 4)
void spil_kernel(const float* __restrict__ cxyz_g,  const float* __restrict__ cfeat_g,
                 const float* __restrict__ nxyz_g,  const float* __restrict__ nfeat_g,
                 const float* __restrict__ phi_w,   const float* __restrict__ phi_b,
                 const float* __restrict__ theta_w, const float* __restrict__ theta_b,
                 const float* __restrict__ z_w,     const float* __restrict__ z_b,
                 float* __restrict__ out)
{
    extern __shared__ __align__(16) char smem[];
    float* sc = (float*)(smem + SM_SCAL);
    const uint32_t sbase = smem_u32(smem);
    const int tid = threadIdx.x;
    const int wid = tid >> 5, lid = tid & 31;
    const int g = lid >> 2, tg = lid & 3;
    const long g0 = (long)blockIdx.x * 4;

    // ================= P1: stage A + phi partials + s_i ===========================
    const float4* nf4 = (const float4*)(nfeat_g + g0 * (KNN * C_));
    #pragma unroll 4
    for (int it = 0; it < 16; it++) {
        int i = tid + it * 256;
        float4 v = nf4[i];
        int f = i << 2;
        int r = f >> 7, c = f & 127;
        __half2 h0 = __floats2half2_rn(v.x, v.y);
        __half2 h1 = __floats2half2_rn(v.z, v.w);
        uint2 uv = make_uint2(*(uint32_t*)&h0, *(uint32_t*)&h1);
        *(uint2*)(smem + SM_A + (r * SAH_STR + c) * 2) = uv;
    }
    // s_i (uniform const weights)
    if (tid < 4) {
        float x = cxyz_g[(g0 + tid) * 3], y = cxyz_g[(g0 + tid) * 3 + 1],
              z = cxyz_g[(g0 + tid) * 3 + 2];
        float s = C_PSB[0];
        #pragma unroll 8
        for (int j = 0; j < 32; j++) {
            float v = C_M1B[j] + x * C_M1W[j] + y * C_M1W[32 + j] + z * C_M1W[64 + j];
            s = fmaf(fmaxf(v, 0.f), C_PSW[j], s);
        }
        sc[OF_SI + tid] = s;
    }
    // phi partials: thread (h, cc); phi_w read once per CTA
    {
        const int h = tid & 63, cc = tid >> 6;
        const int cbeg = cc * 32;
        float a0 = 0.f, a1 = 0.f, a2 = 0.f, a3 = 0.f;
        const float* cf = cfeat_g + g0 * C_;
        #pragma unroll 2
        for (int cq = 0; cq < 8; cq++) {
            int c0 = cbeg + cq * 4;
            float4 f0 = *(const float4*)&cf[c0];
            float4 f1 = *(const float4*)&cf[128 + c0];
            float4 f2 = *(const float4*)&cf[256 + c0];
            float4 f3 = *(const float4*)&cf[384 + c0];
            float w0 = phi_w[(c0 + 0) * 64 + h];
            float w1 = phi_w[(c0 + 1) * 64 + h];
            float w2 = phi_w[(c0 + 2) * 64 + h];
            float w3 = phi_w[(c0 + 3) * 64 + h];
            a0 = fmaf(f0.x, w0, fmaf(f0.y, w1, fmaf(f0.z, w2, fmaf(f0.w, w3, a0))));
            a1 = fmaf(f1.x, w0, fmaf(f1.y, w1, fmaf(f1.z, w2, fmaf(f1.w, w3, a1))));
            a2 = fmaf(f2.x, w0, fmaf(f2.y, w1, fmaf(f2.z, w2, fmaf(f2.w, w3, a2))));
            a3 = fmaf(f3.x, w0, fmaf(f3.y, w1, fmaf(f3.z, w2, fmaf(f3.w, w3, a3))));
        }
        sc[OF_P + (cc * 4 + 0) * 64 + h] = a0;
        sc[OF_P + (cc * 4 + 1) * 64 + h] = a1;
        sc[OF_P + (cc * 4 + 2) * 64 + h] = a2;
        sc[OF_P + (cc * 4 + 3) * 64 + h] = a3;
    }
    __syncthreads();

    // ================= P2: r_l (tid<128, const weights) || FI reduce ==============
    if (tid < 128) {
        const int r = tid, pp = r >> 5;
        float nx = nxyz_g[g0 * 96 + r * 3], ny = nxyz_g[g0 * 96 + r * 3 + 1],
              nz = nxyz_g[g0 * 96 + r * 3 + 2];
        float cx = cxyz_g[(g0 + pp) * 3], cy = cxyz_g[(g0 + pp) * 3 + 1],
              cz = cxyz_g[(g0 + pp) * 3 + 2];
        float acc = sc[OF_SI + pp];
        #pragma unroll 8
        for (int j = 0; j < 32; j++) {
            float v = C_M2B[j] + nx * C_M2W[j] + ny * C_M2W[32 + j] + nz * C_M2W[64 + j];
            acc = fmaf(fmaxf(v, 0.f), C_PSW[32 + j], acc);
        }
        float rl = fmaxf(acc, 0.f);
        float dx = cx - nx, dy = cy - ny, dz = cz - nz;
        if (cz == nz && dx * dx + dy * dy + dz * dz > 0.0016f) rl = 0.f;  // SPIL mask
        sc[OF_RL + r] = rl;
    } else {
        #pragma unroll
        for (int e = 0; e < 2; e++) {
            int i = (tid - 128) * 2 + e;
            int pp = i >> 6, h = i & 63;
            float v = sc[OF_P + pp * 64 + h] + sc[OF_P + (4 + pp) * 64 + h]
                    + sc[OF_P + (8 + pp) * 64 + h] + sc[OF_P + (12 + pp) * 64 + h]
                    + phi_b[h];
            sc[OF_FI + i] = fmaxf(v, 0.f);
        }
    }
    __syncthreads();

    // ================= P3: MMA m32n32 (warp w: point w>>1, n-half w&1) ============
    const int p = wid >> 1, nh = wid & 1;
    float dacc[2][4][4];
    #pragma unroll
    for (int mt = 0; mt < 2; mt++)
        #pragma unroll
        for (int t = 0; t < 4; t++)
            #pragma unroll
            for (int j = 0; j < 4; j++) dacc[mt][t][j] = 0.f;
    {
        const uint32_t aa0 = sbase + SM_A
            + (uint32_t)(((p * 32 + (lid & 15)) * SAH_STR + ((lid >> 4) * 8)) * 2);
        const uint32_t aa1 = aa0 + (uint32_t)(16 * SAH_STR * 2);
        #pragma unroll
        for (int kc = 0; kc < 8; kc++) {
            uint32_t x0, x1, x2, x3, y0, y1, y2, y3;
            asm volatile("ldmatrix.sync.aligned.m8n8.x4.shared.b16 {%0,%1,%2,%3}, [%4];"
                         : "=r"(x0), "=r"(x1), "=r"(x2), "=r"(x3)
                         : "r"(aa0 + (uint32_t)(kc * 32)));
            asm volatile("ldmatrix.sync.aligned.m8n8.x4.shared.b16 {%0,%1,%2,%3}, [%4];"
                         : "=r"(y0), "=r"(y1), "=r"(y2), "=r"(y3)
                         : "r"(aa1 + (uint32_t)(kc * 32)));
            float4 bv0 = __ldg(&g_Bh[kc * 128 + (2 * nh) * 32 + lid]);
            float4 bv1 = __ldg(&g_Bh[kc * 128 + (2 * nh + 1) * 32 + lid]);
            uint32_t b0 = __float_as_uint(bv0.x), b1 = __float_as_uint(bv0.y);
            uint32_t b2 = __float_as_uint(bv0.z), b3 = __float_as_uint(bv0.w);
            uint32_t b4 = __float_as_uint(bv1.x), b5 = __float_as_uint(bv1.y);
            uint32_t b6 = __float_as_uint(bv1.z), b7 = __float_as_uint(bv1.w);
            mma_f16(dacc[0][0], x0, x1, x2, x3, b0, b1);
            mma_f16(dacc[0][1], x0, x1, x2, x3, b2, b3);
            mma_f16(dacc[0][2], x0, x1, x2, x3, b4, b5);
            mma_f16(dacc[0][3], x0, x1, x2, x3, b6, b7);
            mma_f16(dacc[1][0], y0, y1, y2, y3, b0, b1);
            mma_f16(dacc[1][1], y0, y1, y2, y3, b2, b3);
            mma_f16(dacc[1][2], y0, y1, y2, y3, b4, b5);
            mma_f16(dacc[1][3], y0, y1, y2, y3, b6, b7);
        }
    }
    // rf partials: dot with FI, quad-reduce + transpose
    {
        float rfp[4] = {0.f, 0.f, 0.f, 0.f};
        #pragma unroll
        for (int t = 0; t < 4; t++) {
            int h0 = nh * 32 + t * 8 + 2 * tg;
            float2 fi = *(const float2*)&sc[OF_FI + p * 64 + h0];
            float2 tb = *(const float2*)&theta_b[h0];
            rfp[0] = fmaf(fi.x, fmaxf(dacc[0][t][0] + tb.x, 0.f),
                     fmaf(fi.y, fmaxf(dacc[0][t][1] + tb.y, 0.f), rfp[0]));
            rfp[1] = fmaf(fi.x, fmaxf(dacc[0][t][2] + tb.x, 0.f),
                     fmaf(fi.y, fmaxf(dacc[0][t][3] + tb.y, 0.f), rfp[1]));
            rfp[2] = fmaf(fi.x, fmaxf(dacc[1][t][0] + tb.x, 0.f),
                     fmaf(fi.y, fmaxf(dacc[1][t][1] + tb.y, 0.f), rfp[2]));
            rfp[3] = fmaf(fi.x, fmaxf(dacc[1][t][2] + tb.x, 0.f),
                     fmaf(fi.y, fmaxf(dacc[1][t][3] + tb.y, 0.f), rfp[3]));
        }
        #pragma unroll
        for (int j = 0; j < 4; j++) {
            rfp[j] += __shfl_xor_sync(0xFFFFFFFFu, rfp[j], 1);
            rfp[j] += __shfl_xor_sync(0xFFFFFFFFu, rfp[j], 2);
        }
        sc[OF_RFP + wid * 32 + g + 8 * tg] = rfp[tg];
    }
    __syncthreads();

    // ================= P4: softmax (warps 0-3; warp p, lane k) ====================
    if (wid < 4) {
        const int k = lid, r = wid * KNN + k;
        float rf = (sc[OF_RFP + (2 * wid) * 32 + k] + sc[OF_RFP + (2 * wid + 1) * 32 + k])
                 * 0.125f;   // 1/sqrt(H)
        float rl = sc[OF_RL + r];
        float m = rf;
        #pragma unroll
        for (int o = 16; o; o >>= 1) m = fmaxf(m, __shfl_xor_sync(0xFFFFFFFFu, m, o));
        float e = rl * __expf(rf - m);
        float s = e;
        #pragma unroll
        for (int o = 16; o; o >>= 1) s += __shfl_xor_sync(0xFFFFFFFFu, s, o);
        float inv = 1.f / (s + 1e-8f);
        sc[OF_W + r] = e * inv;
        if (k == 0) sc[OF_SW + wid] = s * inv;
    }
    __syncthreads();

    // ================= P5: agg k-half partials (warp w: point w>>1, k-half w&1) ===
    {
        const int kh = wid & 1;
        const int c0 = 4 * lid;
        const char* ab = smem + SM_A + ((p * 32 + kh * 16) * SAH_STR + c0) * 2;
        float4 acc = make_float4(0.f, 0.f, 0.f, 0.f);
        #pragma unroll 8
        for (int k = 0; k < 16; k++) {
            float wk = sc[OF_W + p * KNN + kh * 16 + k];
            uint2 uv = *(const uint2*)(ab + k * (SAH_STR * 2));
            float2 f0 = __half22float2(*(__half2*)&uv.x);
            float2 f1 = __half22float2(*(__half2*)&uv.y);
            acc.x = fmaf(wk, f0.x, acc.x);
            acc.y = fmaf(wk, f0.y, acc.y);
            acc.z = fmaf(wk, f1.x, acc.z);
            acc.w = fmaf(wk, f1.y, acc.w);
        }
        *(float4*)&sc[OF_AGP + (p * 2 + kh) * 128 + c0] = acc;
    }
    __syncthreads();

    // ================= P5b: combine k-halves + transpose -> agT[c] = {p0,p1,p2,p3}
    if (tid < 128) {
        const int c = tid;
        float4 v;
        v.x = sc[OF_AGP + 0 * 128 + c] + sc[OF_AGP + 1 * 128 + c];
        v.y = sc[OF_AGP + 2 * 128 + c] + sc[OF_AGP + 3 * 128 + c];
        v.z = sc[OF_AGP + 4 * 128 + c] + sc[OF_AGP + 5 * 128 + c];
        v.w = sc[OF_AGP + 6 * 128 + c] + sc[OF_AGP + 7 * 128 + c];
        *(float4*)&sc[OF_AGT + 4 * c] = v;
    }
    __syncthreads();

    // ================= P6: z partials — one broadcast per channel =================
    {
        const int h = tid & 63, cc = tid >> 6;
        float a0 = 0.f, a1 = 0.f, a2 = 0.f, a3 = 0.f;
        #pragma unroll 8
        for (int j = 0; j < 32; j++) {
            int c = cc * 32 + j;
            float4 ag = *(const float4*)&sc[OF_AGT + 4 * c];
            float w = z_w[c * 64 + h];
            a0 = fmaf(ag.x, w, a0);
            a1 = fmaf(ag.y, w, a1);
            a2 = fmaf(ag.z, w, a2);
            a3 = fmaf(ag.w, w, a3);
        }
        sc[OF_P + (cc * 4 + 0) * 64 + h] = a0;
        sc[OF_P + (cc * 4 + 1) * 64 + h] = a1;
        sc[OF_P + (cc * 4 + 2) * 64 + h] = a2;
        sc[OF_P + (cc * 4 + 3) * 64 + h] = a3;
    }
    __syncthreads();

    // ================= P7: z reduce + hoisted bias + write ========================
    {
        const int pp = tid >> 6, h = tid & 63;
        float v = sc[OF_P + pp * 64 + h] + sc[OF_P + (4 + pp) * 64 + h]
                + sc[OF_P + (8 + pp) * 64 + h] + sc[OF_P + (12 + pp) * 64 + h]
                + sc[OF_SW + pp] * z_b[h];
        out[(g0 + pp) * H_ + h] = v;
    }
}

extern "C" void kernel_launch(void* const* d_in, const int* in_sizes, int n_in,
                              void* d_out, int out_size) {
    (void)in_sizes; (void)n_in; (void)out_size;
    cudaFuncSetAttribute(spil_kernel, cudaFuncAttributeMaxDynamicSharedMemorySize, SMEM_BYTES);

    // lane-uniform weights -> constant bank (DtoD async copies: graph-capturable)
    void* sym;
    cudaGetSymbolAddress(&sym, C_M1W);
    cudaMemcpyAsync(sym, d_in[8], 96 * 4, cudaMemcpyDeviceToDevice);
    cudaGetSymbolAddress(&sym, C_M1B);
    cudaMemcpyAsync(sym, d_in[9], 32 * 4, cudaMemcpyDeviceToDevice);
    cudaGetSymbolAddress(&sym, C_M2W);
    cudaMemcpyAsync(sym, d_in[10], 96 * 4, cudaMemcpyDeviceToDevice);
    cudaGetSymbolAddress(&sym, C_M2B);
    cudaMemcpyAsync(sym, d_in[11], 32 * 4, cudaMemcpyDeviceToDevice);
    cudaGetSymbolAddress(&sym, C_PSW);
    cudaMemcpyAsync(sym, d_in[12], 64 * 4, cudaMemcpyDeviceToDevice);
    cudaGetSymbolAddress(&sym, C_PSB);
    cudaMemcpyAsync(sym, d_in[13], 1 * 4, cudaMemcpyDeviceToDevice);

    pack_theta<<<4, 256>>>((const float*)d_in[6]);
    spil_kernel<<<8192, 256, SMEM_BYTES>>>(
        (const float*)d_in[0],  (const float*)d_in[1],
        (const float*)d_in[2],  (const float*)d_in[3],
        (const float*)d_in[4],  (const float*)d_in[5],
        (const float*)d_in[6],  (const float*)d_in[7],
        (const float*)d_in[14], (const float*)d_in[15],
        (float*)d_out);
}

// round 10
// speedup vs baseline: 2.0166x; 1.0013x over previous
#include <cuda_runtime.h>
#include <cuda_fp16.h>
#include <cstdint>

// SPIL layer, fused — sm_103-safe mma.sync.m16n8k16.f16.
// One CTA = 4 points (128 neighbor rows). 256 threads, 4 CTAs/SM (~42KB smem, 64 regs).
// P3: theta MMA m32n32/warp (B frags prepacked, L2-resident).
// Epilogue fully on tensor pipe:
//   MMA-2: agg[4,128] = W(fp16, block-diag 4x128) @ nf-tile  (B via ldmatrix.trans)
//   MMA-3: out[4,64]  = agg(fp16) @ z_w(prepacked frags) + sumW*z_b
// Lane-uniform MLP weights in __constant__.

#define KNN 32
#define C_ 128
#define H_ 64

static constexpr int SAH_STR = 136;   // A stride in halves; LDSM/ldmatrix conflict-free
static constexpr int SM_A    = 0;     // 128 x 136 fp16 = 34816 B
static constexpr int SM_SCAL = 34816; // scalar float region
// float offsets inside scalar region
static constexpr int OF_FI  = 0;     // feat_i 4x64
static constexpr int OF_RFP = 256;   // rf partials per warp [8][32]
static constexpr int OF_RL  = 512;   // r_l (masked) 128
static constexpr int OF_W   = 640;   // W_ij as fp16 (64 floats = 128 halves)
static constexpr int OF_SW  = 768;   // sumW 4
static constexpr int OF_SI  = 772;   // s_i 4
static constexpr int OF_P   = 776;   // phi partials 16x64; agg_h (4x128 fp16) overlays later
static constexpr int SMEM_BYTES = SM_SCAL + 1800 * 4;   // 42016 B -> 4 CTAs/SM

// lane-uniform weights -> constant bank
__constant__ float C_M1W[96];
__constant__ float C_M1B[32];
__constant__ float C_M2W[96];
__constant__ float C_M2B[32];
__constant__ float C_PSW[64];
__constant__ float C_PSB[1];

// theta_w packed as fp16 B-fragments: [kc][j(n16)][lane] float4 (b0,b1 of 2 n8-tiles)
__device__ float4 g_Bh[1024];
// z_w packed as fp16 B-fragments: [kc][nt(n8)][lane] float2 (b0,b1)
__device__ float2 g_Bz[2048];

__global__ void pack_weights(const float* __restrict__ theta_w,
                             const float* __restrict__ z_w) {
    int i = blockIdx.x * blockDim.x + threadIdx.x;
    if (i < 1024) {
        int lane = i & 31, j = (i >> 5) & 3, kc = i >> 7;
        int g = lane >> 2, tg = lane & 3;
        int k0 = kc * 16 + 2 * tg;
        int n0 = j * 16 + g, n1 = n0 + 8;
        __half2 u0 = __floats2half2_rn(theta_w[k0 * 64 + n0], theta_w[(k0 + 1) * 64 + n0]);
        __half2 u1 = __floats2half2_rn(theta_w[(k0 + 8) * 64 + n0], theta_w[(k0 + 9) * 64 + n0]);
        __half2 u2 = __floats2half2_rn(theta_w[k0 * 64 + n1], theta_w[(k0 + 1) * 64 + n1]);
        __half2 u3 = __floats2half2_rn(theta_w[(k0 + 8) * 64 + n1], theta_w[(k0 + 9) * 64 + n1]);
        float4 v;
        v.x = __uint_as_float(*(uint32_t*)&u0);
        v.y = __uint_as_float(*(uint32_t*)&u1);
        v.z = __uint_as_float(*(uint32_t*)&u2);
        v.w = __uint_as_float(*(uint32_t*)&u3);
        g_Bh[i] = v;
    } else if (i < 3072) {
        int j = i - 1024;
        int lane = j & 31, nt = (j >> 5) & 7, kc = j >> 8;
        int g = lane >> 2, tg = lane & 3;
        int k0 = kc * 16 + 2 * tg;
        int h = nt * 8 + g;
        __half2 u0 = __floats2half2_rn(z_w[k0 * 64 + h], z_w[(k0 + 1) * 64 + h]);
        __half2 u1 = __floats2half2_rn(z_w[(k0 + 8) * 64 + h], z_w[(k0 + 9) * 64 + h]);
        float2 v;
        v.x = __uint_as_float(*(uint32_t*)&u0);
        v.y = __uint_as_float(*(uint32_t*)&u1);
        g_Bz[j] = v;
    }
}

__device__ __forceinline__ uint32_t smem_u32(const void* p) {
    uint32_t a;
    asm("{ .reg .u64 t; cvta.to.shared.u64 t, %1; cvt.u32.u64 %0, t; }" : "=r"(a) : "l"(p));
    return a;
}

__device__ __forceinline__ void mma_f16(float* d, uint32_t a0, uint32_t a1, uint32_t a2,
                                        uint32_t a3, uint32_t b0, uint32_t b1) {
    asm volatile(
        "mma.sync.aligned.m16n8k16.row.col.f32.f16.f16.f32 "
        "{%0,%1,%2,%3}, {%4,%5,%6,%7}, {%8,%9}, {%0,%1,%2,%3};"
        : "+f"(d[0]), "+f"(d[1]), "+f"(d[2]), "+f"(d[3])
        : "r"(a0), "r"(a1), "r"(a2), "r"(a3), "r"(b0), "r"(b1));
}

__global__ __launch_bounds__(256, 4)
void spil_kernel(const float* __restrict__ cxyz_g,  const float* __restrict__ cfeat_g,
                 const float* __restrict__ nxyz_g,  const float* __restrict__ nfeat_g,
                 const float* __restrict__ phi_w,   const float* __restrict__ phi_b,
                 const float* __restrict__ theta_b, const float* __restrict__ z_b,
                 float* __restrict__ out)
{
    extern __shared__ __align__(16) char smem[];
    float* sc = (float*)(smem + SM_SCAL);
    const uint32_t sbase = smem_u32(smem);
    const int tid = threadIdx.x;
    const int wid = tid >> 5, lid = tid & 31;
    const int g = lid >> 2, tg = lid & 3;
    const long g0 = (long)blockIdx.x * 4;

    // ================= P1: stage A + phi partials + s_i ===========================
    const float4* nf4 = (const float4*)(nfeat_g + g0 * (KNN * C_));
    #pragma unroll 4
    for (int it = 0; it < 16; it++) {
        int i = tid + it * 256;
        float4 v = nf4[i];
        int f = i << 2;
        int r = f >> 7, c = f & 127;
        __half2 h0 = __floats2half2_rn(v.x, v.y);
        __half2 h1 = __floats2half2_rn(v.z, v.w);
        uint2 uv = make_uint2(*(uint32_t*)&h0, *(uint32_t*)&h1);
        *(uint2*)(smem + SM_A + (r * SAH_STR + c) * 2) = uv;
    }
    if (tid < 4) {
        float x = cxyz_g[(g0 + tid) * 3], y = cxyz_g[(g0 + tid) * 3 + 1],
              z = cxyz_g[(g0 + tid) * 3 + 2];
        float s = C_PSB[0];
        #pragma unroll 8
        for (int j = 0; j < 32; j++) {
            float v = C_M1B[j] + x * C_M1W[j] + y * C_M1W[32 + j] + z * C_M1W[64 + j];
            s = fmaf(fmaxf(v, 0.f), C_PSW[j], s);
        }
        sc[OF_SI + tid] = s;
    }
    {
        const int h = tid & 63, cc = tid >> 6;
        const int cbeg = cc * 32;
        float a0 = 0.f, a1 = 0.f, a2 = 0.f, a3 = 0.f;
        const float* cf = cfeat_g + g0 * C_;
        #pragma unroll 2
        for (int cq = 0; cq < 8; cq++) {
            int c0 = cbeg + cq * 4;
            float4 f0 = *(const float4*)&cf[c0];
            float4 f1 = *(const float4*)&cf[128 + c0];
            float4 f2 = *(const float4*)&cf[256 + c0];
            float4 f3 = *(const float4*)&cf[384 + c0];
            float w0 = phi_w[(c0 + 0) * 64 + h];
            float w1 = phi_w[(c0 + 1) * 64 + h];
            float w2 = phi_w[(c0 + 2) * 64 + h];
            float w3 = phi_w[(c0 + 3) * 64 + h];
            a0 = fmaf(f0.x, w0, fmaf(f0.y, w1, fmaf(f0.z, w2, fmaf(f0.w, w3, a0))));
            a1 = fmaf(f1.x, w0, fmaf(f1.y, w1, fmaf(f1.z, w2, fmaf(f1.w, w3, a1))));
            a2 = fmaf(f2.x, w0, fmaf(f2.y, w1, fmaf(f2.z, w2, fmaf(f2.w, w3, a2))));
            a3 = fmaf(f3.x, w0, fmaf(f3.y, w1, fmaf(f3.z, w2, fmaf(f3.w, w3, a3))));
        }
        sc[OF_P + (cc * 4 + 0) * 64 + h] = a0;
        sc[OF_P + (cc * 4 + 1) * 64 + h] = a1;
        sc[OF_P + (cc * 4 + 2) * 64 + h] = a2;
        sc[OF_P + (cc * 4 + 3) * 64 + h] = a3;
    }
    __syncthreads();

    // ================= P2: r_l (tid<128) || FI reduce =============================
    if (tid < 128) {
        const int r = tid, pp = r >> 5;
        float nx = nxyz_g[g0 * 96 + r * 3], ny = nxyz_g[g0 * 96 + r * 3 + 1],
              nz = nxyz_g[g0 * 96 + r * 3 + 2];
        float cx = cxyz_g[(g0 + pp) * 3], cy = cxyz_g[(g0 + pp) * 3 + 1],
              cz = cxyz_g[(g0 + pp) * 3 + 2];
        float acc = sc[OF_SI + pp];
        #pragma unroll 8
        for (int j = 0; j < 32; j++) {
            float v = C_M2B[j] + nx * C_M2W[j] + ny * C_M2W[32 + j] + nz * C_M2W[64 + j];
            acc = fmaf(fmaxf(v, 0.f), C_PSW[32 + j], acc);
        }
        float rl = fmaxf(acc, 0.f);
        float dx = cx - nx, dy = cy - ny, dz = cz - nz;
        if (cz == nz && dx * dx + dy * dy + dz * dz > 0.0016f) rl = 0.f;  // SPIL mask
        sc[OF_RL + r] = rl;
    } else {
        #pragma unroll
        for (int e = 0; e < 2; e++) {
            int i = (tid - 128) * 2 + e;
            int pp = i >> 6, h = i & 63;
            float v = sc[OF_P + pp * 64 + h] + sc[OF_P + (4 + pp) * 64 + h]
                    + sc[OF_P + (8 + pp) * 64 + h] + sc[OF_P + (12 + pp) * 64 + h]
                    + phi_b[h];
            sc[OF_FI + i] = fmaxf(v, 0.f);
        }
    }
    __syncthreads();

    // ================= P3: theta MMA m32n32 (warp: point wid>>1, n-half wid&1) ====
    const int p = wid >> 1, nh = wid & 1;
    {
        float dacc[2][4][4];
        #pragma unroll
        for (int mt = 0; mt < 2; mt++)
            #pragma unroll
            for (int t = 0; t < 4; t++)
                #pragma unroll
                for (int j = 0; j < 4; j++) dacc[mt][t][j] = 0.f;
        const uint32_t aa0 = sbase + SM_A
            + (uint32_t)(((p * 32 + (lid & 15)) * SAH_STR + ((lid >> 4) * 8)) * 2);
        const uint32_t aa1 = aa0 + (uint32_t)(16 * SAH_STR * 2);
        #pragma unroll
        for (int kc = 0; kc < 8; kc++) {
            uint32_t x0, x1, x2, x3, y0, y1, y2, y3;
            asm volatile("ldmatrix.sync.aligned.m8n8.x4.shared.b16 {%0,%1,%2,%3}, [%4];"
                         : "=r"(x0), "=r"(x1), "=r"(x2), "=r"(x3)
                         : "r"(aa0 + (uint32_t)(kc * 32)));
            asm volatile("ldmatrix.sync.aligned.m8n8.x4.shared.b16 {%0,%1,%2,%3}, [%4];"
                         : "=r"(y0), "=r"(y1), "=r"(y2), "=r"(y3)
                         : "r"(aa1 + (uint32_t)(kc * 32)));
            float4 bv0 = __ldg(&g_Bh[kc * 128 + (2 * nh) * 32 + lid]);
            float4 bv1 = __ldg(&g_Bh[kc * 128 + (2 * nh + 1) * 32 + lid]);
            uint32_t b0 = __float_as_uint(bv0.x), b1 = __float_as_uint(bv0.y);
            uint32_t b2 = __float_as_uint(bv0.z), b3 = __float_as_uint(bv0.w);
            uint32_t b4 = __float_as_uint(bv1.x), b5 = __float_as_uint(bv1.y);
            uint32_t b6 = __float_as_uint(bv1.z), b7 = __float_as_uint(bv1.w);
            mma_f16(dacc[0][0], x0, x1, x2, x3, b0, b1);
            mma_f16(dacc[0][1], x0, x1, x2, x3, b2, b3);
            mma_f16(dacc[0][2], x0, x1, x2, x3, b4, b5);
            mma_f16(dacc[0][3], x0, x1, x2, x3, b6, b7);
            mma_f16(dacc[1][0], y0, y1, y2, y3, b0, b1);
            mma_f16(dacc[1][1], y0, y1, y2, y3, b2, b3);
            mma_f16(dacc[1][2], y0, y1, y2, y3, b4, b5);
            mma_f16(dacc[1][3], y0, y1, y2, y3, b6, b7);
        }
        // rf partials: dot with FI, quad-reduce + transpose
        float rfp[4] = {0.f, 0.f, 0.f, 0.f};
        #pragma unroll
        for (int t = 0; t < 4; t++) {
            int h0 = nh * 32 + t * 8 + 2 * tg;
            float2 fi = *(const float2*)&sc[OF_FI + p * 64 + h0];
            float2 tb = *(const float2*)&theta_b[h0];
            rfp[0] = fmaf(fi.x, fmaxf(dacc[0][t][0] + tb.x, 0.f),
                     fmaf(fi.y, fmaxf(dacc[0][t][1] + tb.y, 0.f), rfp[0]));
            rfp[1] = fmaf(fi.x, fmaxf(dacc[0][t][2] + tb.x, 0.f),
                     fmaf(fi.y, fmaxf(dacc[0][t][3] + tb.y, 0.f), rfp[1]));
            rfp[2] = fmaf(fi.x, fmaxf(dacc[1][t][0] + tb.x, 0.f),
                     fmaf(fi.y, fmaxf(dacc[1][t][1] + tb.y, 0.f), rfp[2]));
            rfp[3] = fmaf(fi.x, fmaxf(dacc[1][t][2] + tb.x, 0.f),
                     fmaf(fi.y, fmaxf(dacc[1][t][3] + tb.y, 0.f), rfp[3]));
        }
        #pragma unroll
        for (int j = 0; j < 4; j++) {
            rfp[j] += __shfl_xor_sync(0xFFFFFFFFu, rfp[j], 1);
            rfp[j] += __shfl_xor_sync(0xFFFFFFFFu, rfp[j], 2);
        }
        sc[OF_RFP + wid * 32 + g + 8 * tg] = rfp[tg];
    }
    __syncthreads();

    // ================= P4: softmax (warps 0-3), W stored as fp16 ==================
    __half* Wh = (__half*)(sc + OF_W);
    if (wid < 4) {
        const int k = lid, r = wid * KNN + k;
        float rf = (sc[OF_RFP + (2 * wid) * 32 + k] + sc[OF_RFP + (2 * wid + 1) * 32 + k])
                 * 0.125f;   // 1/sqrt(H)
        float rl = sc[OF_RL + r];
        float m = rf;
        #pragma unroll
        for (int o = 16; o; o >>= 1) m = fmaxf(m, __shfl_xor_sync(0xFFFFFFFFu, m, o));
        float e = rl * __expf(rf - m);
        float s = e;
        #pragma unroll
        for (int o = 16; o; o >>= 1) s += __shfl_xor_sync(0xFFFFFFFFu, s, o);
        float inv = 1.f / (s + 1e-8f);
        Wh[r] = __float2half(e * inv);
        if (k == 0) sc[OF_SW + wid] = s * inv;
    }
    __syncthreads();

    // ================= P5: MMA-2  agg[4,128] = W @ nf-tile ========================
    // A = W block-diag (rows 0-3); B = nf tile via ldmatrix.x4.trans, warp w: n16 cols
    __half* aggh = (__half*)(sc + OF_P);  // 4x128 fp16 (phi partials dead)
    {
        float d2[2][4];
        #pragma unroll
        for (int t = 0; t < 2; t++)
            #pragma unroll
            for (int j = 0; j < 4; j++) d2[t][j] = 0.f;
        const int row_l = ((lid >> 3) & 1) * 8 + (lid & 7);
        const uint32_t baddr = sbase + SM_A
            + (uint32_t)((row_l * SAH_STR + wid * 16 + (lid >> 4) * 8) * 2);
        #pragma unroll
        for (int kc = 0; kc < 8; kc++) {
            uint32_t b0, b1, b2, b3;
            asm volatile("ldmatrix.sync.aligned.m8n8.x4.trans.shared.b16 {%0,%1,%2,%3}, [%4];"
                         : "=r"(b0), "=r"(b1), "=r"(b2), "=r"(b3)
                         : "r"(baddr + (uint32_t)(kc * 16 * SAH_STR * 2)));
            uint32_t a0 = 0u, a2 = 0u;
            if (g == (kc >> 1)) {
                const __half* wp = Wh + g * 32 + (kc & 1) * 16 + 2 * tg;
                a0 = *(const uint32_t*)wp;
                a2 = *(const uint32_t*)(wp + 8);
            }
            mma_f16(d2[0], a0, 0u, a2, 0u, b0, b1);
            mma_f16(d2[1], a0, 0u, a2, 0u, b2, b3);
        }
        if (g < 4) {   // rows 0-3 = points; store agg as fp16
            #pragma unroll
            for (int t = 0; t < 2; t++) {
                __half2 hv = __floats2half2_rn(d2[t][0], d2[t][1]);
                *(uint32_t*)&aggh[g * 128 + wid * 16 + t * 8 + 2 * tg] = *(uint32_t*)&hv;
            }
        }
    }
    __syncthreads();

    // ================= P6: MMA-3  out[4,64] = agg @ z_w  (+ sumW*z_b) =============
    {
        float d3[4] = {0.f, 0.f, 0.f, 0.f};
        #pragma unroll
        for (int kc = 0; kc < 8; kc++) {
            uint32_t a0 = 0u, a2 = 0u;
            if (g < 4) {
                const __half* ap = aggh + g * 128 + kc * 16 + 2 * tg;
                a0 = *(const uint32_t*)ap;
                a2 = *(const uint32_t*)(ap + 8);
            }
            float2 bv = __ldg(&g_Bz[kc * 256 + wid * 32 + lid]);
            mma_f16(d3, a0, 0u, a2, 0u, __float_as_uint(bv.x), __float_as_uint(bv.y));
        }
        if (g < 4) {
            int h0 = wid * 8 + 2 * tg;
            float sw = sc[OF_SW + g];
            float2 o;
            o.x = d3[0] + sw * z_b[h0];
            o.y = d3[1] + sw * z_b[h0 + 1];
            *(float2*)&out[(g0 + g) * H_ + h0] = o;
        }
    }
}

extern "C" void kernel_launch(void* const* d_in, const int* in_sizes, int n_in,
                              void* d_out, int out_size) {
    (void)in_sizes; (void)n_in; (void)out_size;
    cudaFuncSetAttribute(spil_kernel, cudaFuncAttributeMaxDynamicSharedMemorySize, SMEM_BYTES);

    void* sym;
    cudaGetSymbolAddress(&sym, C_M1W);
    cudaMemcpyAsync(sym, d_in[8], 96 * 4, cudaMemcpyDeviceToDevice);
    cudaGetSymbolAddress(&sym, C_M1B);
    cudaMemcpyAsync(sym, d_in[9], 32 * 4, cudaMemcpyDeviceToDevice);
    cudaGetSymbolAddress(&sym, C_M2W);
    cudaMemcpyAsync(sym, d_in[10], 96 * 4, cudaMemcpyDeviceToDevice);
    cudaGetSymbolAddress(&sym, C_M2B);
    cudaMemcpyAsync(sym, d_in[11], 32 * 4, cudaMemcpyDeviceToDevice);
    cudaGetSymbolAddress(&sym, C_PSW);
    cudaMemcpyAsync(sym, d_in[12], 64 * 4, cudaMemcpyDeviceToDevice);
    cudaGetSymbolAddress(&sym, C_PSB);
    cudaMemcpyAsync(sym, d_in[13], 1 * 4, cudaMemcpyDeviceToDevice);

    pack_weights<<<12, 256>>>((const float*)d_in[6], (const float*)d_in[14]);
    spil_kernel<<<8192, 256, SMEM_BYTES>>>(
        (const float*)d_in[0], (const float*)d_in[1],
        (const float*)d_in[2], (const float*)d_in[3],
        (const float*)d_in[4], (const float*)d_in[5],
        (const float*)d_in[7], (const float*)d_in[15],
        (float*)d_out);
}

// round 11
// speedup vs baseline: 2.4092x; 1.1947x over previous
#include <cuda_runtime.h>
#include <cuda_fp16.h>
#include <cstdint>

// SPIL layer, fused — sm_103-safe mma.sync.m16n8k16.f16.
// One CTA = 4 points (128 neighbor rows). 256 threads, 4 CTAs/SM (~42KB smem).
// P2: theta MMA m32n32/warp + cf@phi_w MMA m16n32 on warps 0/1 (FI on tensor pipe).
// Epilogue on tensor pipe: agg = W @ nf (ldmatrix.trans), out = agg @ z_w + sumW*z_b.
// Lane-uniform MLP weights in one merged __constant__ block (single memcpy node).

#define KNN 32
#define C_ 128
#define H_ 64

static constexpr int SAH_STR = 136;   // A stride in halves; LDSM conflict-free
static constexpr int SM_A    = 0;     // 128 x 136 fp16 = 34816 B
static constexpr int SM_CF   = 34816; // cf tile 16 x 136 fp16 (rows 0-3 valid) = 4352 B
static constexpr int SM_SCAL = 39168; // scalar float region
// float offsets inside scalar region
static constexpr int OF_FI  = 0;     // feat_i 4x64 (fp32); aggh (4x128 fp16) overlays in P5
static constexpr int OF_RFP = 256;   // rf partials per warp [8][32]
static constexpr int OF_RL  = 512;   // r_l (masked) 128
static constexpr int OF_W   = 640;   // W_ij as fp16 (64 floats = 128 halves)
static constexpr int OF_SW  = 704;   // sumW 4
static constexpr int SMEM_BYTES = SM_SCAL + 708 * 4;   // 42000 B -> 4 CTAs/SM

// merged lane-uniform weights: [0:96) m1_w, [96:128) m1_b, [128:224) m2_w,
// [224:256) m2_b, [256:320) psi_w, [320] psi_b
__constant__ float C_ALL[321];
#define C_M1W (C_ALL)
#define C_M1B (C_ALL + 96)
#define C_M2W (C_ALL + 128)
#define C_M2B (C_ALL + 224)
#define C_PSW (C_ALL + 256)
#define C_PSB (C_ALL + 320)

__device__ float  g_gather[321];   // staging for C_ALL (one DtoD memcpy node)
__device__ float4 g_Bh[1024];      // theta_w fp16 B-frags [kc][j(n16)][lane]
__device__ float4 g_Bp[1024];      // phi_w   fp16 B-frags, same layout
__device__ float2 g_Bz[2048];      // z_w     fp16 B-frags [kc][nt(n8)][lane]

__global__ void pack_weights(const float* __restrict__ theta_w,
                             const float* __restrict__ phi_w,
                             const float* __restrict__ z_w,
                             const float* __restrict__ m1_w, const float* __restrict__ m1_b,
                             const float* __restrict__ m2_w, const float* __restrict__ m2_b,
                             const float* __restrict__ psi_w, const float* __restrict__ psi_b) {
    int i = blockIdx.x * blockDim.x + threadIdx.x;
    if (i < 2048) {   // theta (0..1023) and phi (1024..2047), identical layout
        const float* src = (i < 1024) ? theta_w : phi_w;
        int ii = i & 1023;
        int lane = ii & 31, j = (ii >> 5) & 3, kc = ii >> 7;
        int g = lane >> 2, tg = lane & 3;
        int k0 = kc * 16 + 2 * tg;
        int n0 = j * 16 + g, n1 = n0 + 8;
        __half2 u0 = __floats2half2_rn(src[k0 * 64 + n0], src[(k0 + 1) * 64 + n0]);
        __half2 u1 = __floats2half2_rn(src[(k0 + 8) * 64 + n0], src[(k0 + 9) * 64 + n0]);
        __half2 u2 = __floats2half2_rn(src[k0 * 64 + n1], src[(k0 + 1) * 64 + n1]);
        __half2 u3 = __floats2half2_rn(src[(k0 + 8) * 64 + n1], src[(k0 + 9) * 64 + n1]);
        float4 v;
        v.x = __uint_as_float(*(uint32_t*)&u0);
        v.y = __uint_as_float(*(uint32_t*)&u1);
        v.z = __uint_as_float(*(uint32_t*)&u2);
        v.w = __uint_as_float(*(uint32_t*)&u3);
        if (i < 1024) g_Bh[ii] = v; else g_Bp[ii] = v;
    } else if (i < 4096) {   // z_w
        int j = i - 2048;
        int lane = j & 31, nt = (j >> 5) & 7, kc = j >> 8;
        int g = lane >> 2, tg = lane & 3;
        int k0 = kc * 16 + 2 * tg;
        int h = nt * 8 + g;
        __half2 u0 = __floats2half2_rn(z_w[k0 * 64 + h], z_w[(k0 + 1) * 64 + h]);
        __half2 u1 = __floats2half2_rn(z_w[(k0 + 8) * 64 + h], z_w[(k0 + 9) * 64 + h]);
        float2 v;
        v.x = __uint_as_float(*(uint32_t*)&u0);
        v.y = __uint_as_float(*(uint32_t*)&u1);
        g_Bz[j] = v;
    } else if (i < 4417) {   // gather lane-uniform weights
        int j = i - 4096;
        float v;
        if (j < 96)       v = m1_w[j];
        else if (j < 128) v = m1_b[j - 96];
        else if (j < 224) v = m2_w[j - 128];
        else if (j < 256) v = m2_b[j - 224];
        else if (j < 320) v = psi_w[j - 256];
        else              v = psi_b[0];
        g_gather[j] = v;
    }
}

__device__ __forceinline__ uint32_t smem_u32(const void* p) {
    uint32_t a;
    asm("{ .reg .u64 t; cvta.to.shared.u64 t, %1; cvt.u32.u64 %0, t; }" : "=r"(a) : "l"(p));
    return a;
}

__device__ __forceinline__ void mma_f16(float* d, uint32_t a0, uint32_t a1, uint32_t a2,
                                        uint32_t a3, uint32_t b0, uint32_t b1) {
    asm volatile(
        "mma.sync.aligned.m16n8k16.row.col.f32.f16.f16.f32 "
        "{%0,%1,%2,%3}, {%4,%5,%6,%7}, {%8,%9}, {%0,%1,%2,%3};"
        : "+f"(d[0]), "+f"(d[1]), "+f"(d[2]), "+f"(d[3])
        : "r"(a0), "r"(a1), "r"(a2), "r"(a3), "r"(b0), "r"(b1));
}

__global__ __launch_bounds__(256, 4)
void spil_kernel(const float* __restrict__ cxyz_g,  const float* __restrict__ cfeat_g,
                 const float* __restrict__ nxyz_g,  const float* __restrict__ nfeat_g,
                 const float* __restrict__ phi_b,   const float* __restrict__ theta_b,
                 const float* __restrict__ z_b,     float* __restrict__ out)
{
    extern __shared__ __align__(16) char smem[];
    float* sc = (float*)(smem + SM_SCAL);
    const uint32_t sbase = smem_u32(smem);
    const int tid = threadIdx.x;
    const int wid = tid >> 5, lid = tid & 31;
    const int g = lid >> 2, tg = lid & 3;
    const long g0 = (long)blockIdx.x * 4;

    // ================= P1: stage A + stage cf + r_l (s_i inline) ==================
    const float4* nf4 = (const float4*)(nfeat_g + g0 * (KNN * C_));
    #pragma unroll 4
    for (int it = 0; it < 16; it++) {
        int i = tid + it * 256;
        float4 v = nf4[i];
        int f = i << 2;
        int r = f >> 7, c = f & 127;
        __half2 h0 = __floats2half2_rn(v.x, v.y);
        __half2 h1 = __floats2half2_rn(v.z, v.w);
        uint2 uv = make_uint2(*(uint32_t*)&h0, *(uint32_t*)&h1);
        *(uint2*)(smem + SM_A + (r * SAH_STR + c) * 2) = uv;
    }
    if (tid < 128) {
        // r_l for neighbor row r, with s_i computed inline (all const-bank math)
        const int r = tid, pp = r >> 5;
        float nx = nxyz_g[g0 * 96 + r * 3], ny = nxyz_g[g0 * 96 + r * 3 + 1],
              nz = nxyz_g[g0 * 96 + r * 3 + 2];
        float cx = cxyz_g[(g0 + pp) * 3], cy = cxyz_g[(g0 + pp) * 3 + 1],
              cz = cxyz_g[(g0 + pp) * 3 + 2];
        float acc = C_PSB[0];
        #pragma unroll 8
        for (int j = 0; j < 32; j++) {
            float v = C_M1B[j] + cx * C_M1W[j] + cy * C_M1W[32 + j] + cz * C_M1W[64 + j];
            acc = fmaf(fmaxf(v, 0.f), C_PSW[j], acc);
        }
        #pragma unroll 8
        for (int j = 0; j < 32; j++) {
            float v = C_M2B[j] + nx * C_M2W[j] + ny * C_M2W[32 + j] + nz * C_M2W[64 + j];
            acc = fmaf(fmaxf(v, 0.f), C_PSW[32 + j], acc);
        }
        float rl = fmaxf(acc, 0.f);
        float dx = cx - nx, dy = cy - ny, dz = cz - nz;
        if (cz == nz && dx * dx + dy * dy + dz * dz > 0.0016f) rl = 0.f;  // SPIL mask
        sc[OF_RL + r] = rl;
    } else {
        // stage cf (4 rows x 128 cols fp16) into SM_CF rows 0-3 (rows 4-15 garbage OK)
        int i = tid - 128;           // 0..127
        int row = i >> 5, c0 = (i & 31) * 4;
        float4 v = *(const float4*)&cfeat_g[(g0 + row) * C_ + c0];
        __half2 h0 = __floats2half2_rn(v.x, v.y);
        __half2 h1 = __floats2half2_rn(v.z, v.w);
        uint2 uv = make_uint2(*(uint32_t*)&h0, *(uint32_t*)&h1);
        *(uint2*)(smem + SM_CF + (row * SAH_STR + c0) * 2) = uv;
    }
    __syncthreads();

    // ================= P2: MMAs ===================================================
    const int p = wid >> 1, nh = wid & 1;

    // cf @ phi_w on warps 0/1 (m16n32): FI rows 0-3 = points
    if (wid < 2) {
        float dcf[4][4];
        #pragma unroll
        for (int t = 0; t < 4; t++)
            #pragma unroll
            for (int j = 0; j < 4; j++) dcf[t][j] = 0.f;
        const uint32_t cfa = sbase + SM_CF
            + (uint32_t)((((lid & 15)) * SAH_STR + ((lid >> 4) * 8)) * 2);
        #pragma unroll
        for (int kc = 0; kc < 8; kc++) {
            uint32_t a0, a1, a2, a3;
            asm volatile("ldmatrix.sync.aligned.m8n8.x4.shared.b16 {%0,%1,%2,%3}, [%4];"
                         : "=r"(a0), "=r"(a1), "=r"(a2), "=r"(a3)
                         : "r"(cfa + (uint32_t)(kc * 32)));
            float4 bv0 = __ldg(&g_Bp[kc * 128 + (2 * wid) * 32 + lid]);
            float4 bv1 = __ldg(&g_Bp[kc * 128 + (2 * wid + 1) * 32 + lid]);
            mma_f16(dcf[0], a0, a1, a2, a3, __float_as_uint(bv0.x), __float_as_uint(bv0.y));
            mma_f16(dcf[1], a0, a1, a2, a3, __float_as_uint(bv0.z), __float_as_uint(bv0.w));
            mma_f16(dcf[2], a0, a1, a2, a3, __float_as_uint(bv1.x), __float_as_uint(bv1.y));
            mma_f16(dcf[3], a0, a1, a2, a3, __float_as_uint(bv1.z), __float_as_uint(bv1.w));
        }
        if (g < 4) {   // row g = point g; write FI = relu(dcf + phi_b)
            #pragma unroll
            for (int t = 0; t < 4; t++) {
                int h0 = wid * 32 + t * 8 + 2 * tg;
                float2 pb = *(const float2*)&phi_b[h0];
                sc[OF_FI + g * 64 + h0]     = fmaxf(dcf[t][0] + pb.x, 0.f);
                sc[OF_FI + g * 64 + h0 + 1] = fmaxf(dcf[t][1] + pb.y, 0.f);
            }
        }
    }

    // theta MMA m32n32 (warp: point p, n-half nh)
    float dacc[2][4][4];
    #pragma unroll
    for (int mt = 0; mt < 2; mt++)
        #pragma unroll
        for (int t = 0; t < 4; t++)
            #pragma unroll
            for (int j = 0; j < 4; j++) dacc[mt][t][j] = 0.f;
    {
        const uint32_t aa0 = sbase + SM_A
            + (uint32_t)(((p * 32 + (lid & 15)) * SAH_STR + ((lid >> 4) * 8)) * 2);
        const uint32_t aa1 = aa0 + (uint32_t)(16 * SAH_STR * 2);
        #pragma unroll
        for (int kc = 0; kc < 8; kc++) {
            uint32_t x0, x1, x2, x3, y0, y1, y2, y3;
            asm volatile("ldmatrix.sync.aligned.m8n8.x4.shared.b16 {%0,%1,%2,%3}, [%4];"
                         : "=r"(x0), "=r"(x1), "=r"(x2), "=r"(x3)
                         : "r"(aa0 + (uint32_t)(kc * 32)));
            asm volatile("ldmatrix.sync.aligned.m8n8.x4.shared.b16 {%0,%1,%2,%3}, [%4];"
                         : "=r"(y0), "=r"(y1), "=r"(y2), "=r"(y3)
                         : "r"(aa1 + (uint32_t)(kc * 32)));
            float4 bv0 = __ldg(&g_Bh[kc * 128 + (2 * nh) * 32 + lid]);
            float4 bv1 = __ldg(&g_Bh[kc * 128 + (2 * nh + 1) * 32 + lid]);
            uint32_t b0 = __float_as_uint(bv0.x), b1 = __float_as_uint(bv0.y);
            uint32_t b2 = __float_as_uint(bv0.z), b3 = __float_as_uint(bv0.w);
            uint32_t b4 = __float_as_uint(bv1.x), b5 = __float_as_uint(bv1.y);
            uint32_t b6 = __float_as_uint(bv1.z), b7 = __float_as_uint(bv1.w);
            mma_f16(dacc[0][0], x0, x1, x2, x3, b0, b1);
            mma_f16(dacc[0][1], x0, x1, x2, x3, b2, b3);
            mma_f16(dacc[0][2], x0, x1, x2, x3, b4, b5);
            mma_f16(dacc[0][3], x0, x1, x2, x3, b6, b7);
            mma_f16(dacc[1][0], y0, y1, y2, y3, b0, b1);
            mma_f16(dacc[1][1], y0, y1, y2, y3, b2, b3);
            mma_f16(dacc[1][2], y0, y1, y2, y3, b4, b5);
            mma_f16(dacc[1][3], y0, y1, y2, y3, b6, b7);
        }
    }
    __syncthreads();   // FI ready for everyone

    // ================= P3: rf dot from dacc + FI; quad-reduce + transpose =========
    {
        float rfp[4] = {0.f, 0.f, 0.f, 0.f};
        #pragma unroll
        for (int t = 0; t < 4; t++) {
            int h0 = nh * 32 + t * 8 + 2 * tg;
            float2 fi = *(const float2*)&sc[OF_FI + p * 64 + h0];
            float2 tb = *(const float2*)&theta_b[h0];
            rfp[0] = fmaf(fi.x, fmaxf(dacc[0][t][0] + tb.x, 0.f),
                     fmaf(fi.y, fmaxf(dacc[0][t][1] + tb.y, 0.f), rfp[0]));
            rfp[1] = fmaf(fi.x, fmaxf(dacc[0][t][2] + tb.x, 0.f),
                     fmaf(fi.y, fmaxf(dacc[0][t][3] + tb.y, 0.f), rfp[1]));
            rfp[2] = fmaf(fi.x, fmaxf(dacc[1][t][0] + tb.x, 0.f),
                     fmaf(fi.y, fmaxf(dacc[1][t][1] + tb.y, 0.f), rfp[2]));
            rfp[3] = fmaf(fi.x, fmaxf(dacc[1][t][2] + tb.x, 0.f),
                     fmaf(fi.y, fmaxf(dacc[1][t][3] + tb.y, 0.f), rfp[3]));
        }
        #pragma unroll
        for (int j = 0; j < 4; j++) {
            rfp[j] += __shfl_xor_sync(0xFFFFFFFFu, rfp[j], 1);
            rfp[j] += __shfl_xor_sync(0xFFFFFFFFu, rfp[j], 2);
        }
        sc[OF_RFP + wid * 32 + g + 8 * tg] = rfp[tg];
    }
    __syncthreads();

    // ================= P4: softmax (warps 0-3), W stored as fp16 ==================
    __half* Wh = (__half*)(sc + OF_W);
    if (wid < 4) {
        const int k = lid, r = wid * KNN + k;
        float rf = (sc[OF_RFP + (2 * wid) * 32 + k] + sc[OF_RFP + (2 * wid + 1) * 32 + k])
                 * 0.125f;   // 1/sqrt(H)
        float rl = sc[OF_RL + r];
        float m = rf;
        #pragma unroll
        for (int o = 16; o; o >>= 1) m = fmaxf(m, __shfl_xor_sync(0xFFFFFFFFu, m, o));
        float e = rl * __expf(rf - m);
        float s = e;
        #pragma unroll
        for (int o = 16; o; o >>= 1) s += __shfl_xor_sync(0xFFFFFFFFu, s, o);
        float inv = 1.f / (s + 1e-8f);
        Wh[r] = __float2half(e * inv);
        if (k == 0) sc[OF_SW + wid] = s * inv;
    }
    __syncthreads();

    // ================= P5: MMA-2  agg[4,128] = W @ nf-tile ========================
    __half* aggh = (__half*)(sc + OF_FI);  // FI dead after P3
    {
        float d2[2][4];
        #pragma unroll
        for (int t = 0; t < 2; t++)
            #pragma unroll
            for (int j = 0; j < 4; j++) d2[t][j] = 0.f;
        const int row_l = ((lid >> 3) & 1) * 8 + (lid & 7);
        const uint32_t baddr = sbase + SM_A
            + (uint32_t)((row_l * SAH_STR + wid * 16 + (lid >> 4) * 8) * 2);
        #pragma unroll
        for (int kc = 0; kc < 8; kc++) {
            uint32_t b0, b1, b2, b3;
            asm volatile("ldmatrix.sync.aligned.m8n8.x4.trans.shared.b16 {%0,%1,%2,%3}, [%4];"
                         : "=r"(b0), "=r"(b1), "=r"(b2), "=r"(b3)
                         : "r"(baddr + (uint32_t)(kc * 16 * SAH_STR * 2)));
            uint32_t a0 = 0u, a2 = 0u;
            if (g == (kc >> 1)) {
                const __half* wp = Wh + g * 32 + (kc & 1) * 16 + 2 * tg;
                a0 = *(const uint32_t*)wp;
                a2 = *(const uint32_t*)(wp + 8);
            }
            mma_f16(d2[0], a0, 0u, a2, 0u, b0, b1);
            mma_f16(d2[1], a0, 0u, a2, 0u, b2, b3);
        }
        if (g < 4) {
            #pragma unroll
            for (int t = 0; t < 2; t++) {
                __half2 hv = __floats2half2_rn(d2[t][0], d2[t][1]);
                *(uint32_t*)&aggh[g * 128 + wid * 16 + t * 8 + 2 * tg] = *(uint32_t*)&hv;
            }
        }
    }
    __syncthreads();

    // ================= P6: MMA-3  out[4,64] = agg @ z_w  (+ sumW*z_b) =============
    {
        float d3[4] = {0.f, 0.f, 0.f, 0.f};
        #pragma unroll
        for (int kc = 0; kc < 8; kc++) {
            uint32_t a0 = 0u, a2 = 0u;
            if (g < 4) {
                const __half* ap = aggh + g * 128 + kc * 16 + 2 * tg;
                a0 = *(const uint32_t*)ap;
                a2 = *(const uint32_t*)(ap + 8);
            }
            float2 bv = __ldg(&g_Bz[kc * 256 + wid * 32 + lid]);
            mma_f16(d3, a0, 0u, a2, 0u, __float_as_uint(bv.x), __float_as_uint(bv.y));
        }
        if (g < 4) {
            int h0 = wid * 8 + 2 * tg;
            float sw = sc[OF_SW + g];
            float2 o;
            o.x = d3[0] + sw * z_b[h0];
            o.y = d3[1] + sw * z_b[h0 + 1];
            *(float2*)&out[(g0 + g) * H_ + h0] = o;
        }
    }
}

extern "C" void kernel_launch(void* const* d_in, const int* in_sizes, int n_in,
                              void* d_out, int out_size) {
    (void)in_sizes; (void)n_in; (void)out_size;
    cudaFuncSetAttribute(spil_kernel, cudaFuncAttributeMaxDynamicSharedMemorySize, SMEM_BYTES);

    pack_weights<<<18, 256>>>(
        (const float*)d_in[6],  (const float*)d_in[4],  (const float*)d_in[14],
        (const float*)d_in[8],  (const float*)d_in[9],
        (const float*)d_in[10], (const float*)d_in[11],
        (const float*)d_in[12], (const float*)d_in[13]);

    void *dstc, *srcg;
    cudaGetSymbolAddress(&dstc, C_ALL);
    cudaGetSymbolAddress(&srcg, g_gather);
    cudaMemcpyAsync(dstc, srcg, 321 * 4, cudaMemcpyDeviceToDevice);

    spil_kernel<<<8192, 256, SMEM_BYTES>>>(
        (const float*)d_in[0], (const float*)d_in[1],
        (const float*)d_in[2], (const float*)d_in[3],
        (const float*)d_in[5], (const float*)d_in[7],
        (const float*)d_in[15],
        (float*)d_out);
}

// round 12
// speedup vs baseline: 2.4998x; 1.0376x over previous
#include <cuda_runtime.h>
#include <cuda_fp16.h>
#include <cstdint>

// SPIL layer, fused — sm_103-safe mma.sync.m16n8k16.f16.
// One CTA = 4 points (128 neighbor rows). 256 threads, 4 CTAs/SM (~42KB smem).
// P2: theta MMA m32n32/warp (all 8) + cf@phi_w MMA m16n16 spread over warps 4-7.
// Epilogue on tensor pipe: agg = W @ nf (ldmatrix.trans), out = agg @ z_w + sumW*z_b.
// Lane-uniform MLP weights in one merged __constant__ block (single memcpy node).

#define KNN 32
#define C_ 128
#define H_ 64

static constexpr int SAH_STR = 136;   // A stride in halves; LDSM conflict-free
static constexpr int SM_A    = 0;     // 128 x 136 fp16 = 34816 B
static constexpr int SM_CF   = 34816; // cf tile 16 x 136 fp16 (rows 0-3 valid) = 4352 B
static constexpr int SM_SCAL = 39168; // scalar float region
// float offsets inside scalar region
static constexpr int OF_FI  = 0;     // feat_i 4x64 (fp32); aggh (4x128 fp16) overlays in P5
static constexpr int OF_RFP = 256;   // rf partials per warp [8][32]
static constexpr int OF_RL  = 512;   // r_l (masked) 128
static constexpr int OF_W   = 640;   // W_ij as fp16 (128 halves)
static constexpr int OF_SW  = 704;   // sumW 4
static constexpr int SMEM_BYTES = SM_SCAL + 708 * 4;   // 42000 B -> 4 CTAs/SM

// merged lane-uniform weights: [0:96) m1_w, [96:128) m1_b, [128:224) m2_w,
// [224:256) m2_b, [256:320) psi_w, [320] psi_b
__constant__ float C_ALL[321];
#define C_M1W (C_ALL)
#define C_M1B (C_ALL + 96)
#define C_M2W (C_ALL + 128)
#define C_M2B (C_ALL + 224)
#define C_PSW (C_ALL + 256)
#define C_PSB (C_ALL + 320)

__device__ float  g_gather[321];   // staging for C_ALL (one DtoD memcpy node)
__device__ float4 g_Bh[1024];      // theta_w fp16 B-frags [kc][j(n16)][lane]
__device__ float4 g_Bp[1024];      // phi_w   fp16 B-frags, same layout
__device__ float2 g_Bz[2048];      // z_w     fp16 B-frags [kc][nt(n8)][lane]

__global__ void pack_weights(const float* __restrict__ theta_w,
                             const float* __restrict__ phi_w,
                             const float* __restrict__ z_w,
                             const float* __restrict__ m1_w, const float* __restrict__ m1_b,
                             const float* __restrict__ m2_w, const float* __restrict__ m2_b,
                             const float* __restrict__ psi_w, const float* __restrict__ psi_b) {
    int i = blockIdx.x * blockDim.x + threadIdx.x;
    if (i < 2048) {   // theta (0..1023) and phi (1024..2047), identical layout
        const float* src = (i < 1024) ? theta_w : phi_w;
        int ii = i & 1023;
        int lane = ii & 31, j = (ii >> 5) & 3, kc = ii >> 7;
        int g = lane >> 2, tg = lane & 3;
        int k0 = kc * 16 + 2 * tg;
        int n0 = j * 16 + g, n1 = n0 + 8;
        __half2 u0 = __floats2half2_rn(src[k0 * 64 + n0], src[(k0 + 1) * 64 + n0]);
        __half2 u1 = __floats2half2_rn(src[(k0 + 8) * 64 + n0], src[(k0 + 9) * 64 + n0]);
        __half2 u2 = __floats2half2_rn(src[k0 * 64 + n1], src[(k0 + 1) * 64 + n1]);
        __half2 u3 = __floats2half2_rn(src[(k0 + 8) * 64 + n1], src[(k0 + 9) * 64 + n1]);
        float4 v;
        v.x = __uint_as_float(*(uint32_t*)&u0);
        v.y = __uint_as_float(*(uint32_t*)&u1);
        v.z = __uint_as_float(*(uint32_t*)&u2);
        v.w = __uint_as_float(*(uint32_t*)&u3);
        if (i < 1024) g_Bh[ii] = v; else g_Bp[ii] = v;
    } else if (i < 4096) {   // z_w
        int j = i - 2048;
        int lane = j & 31, nt = (j >> 5) & 7, kc = j >> 8;
        int g = lane >> 2, tg = lane & 3;
        int k0 = kc * 16 + 2 * tg;
        int h = nt * 8 + g;
        __half2 u0 = __floats2half2_rn(z_w[k0 * 64 + h], z_w[(k0 + 1) * 64 + h]);
        __half2 u1 = __floats2half2_rn(z_w[(k0 + 8) * 64 + h], z_w[(k0 + 9) * 64 + h]);
        float2 v;
        v.x = __uint_as_float(*(uint32_t*)&u0);
        v.y = __uint_as_float(*(uint32_t*)&u1);
        g_Bz[j] = v;
    } else if (i < 4417) {   // gather lane-uniform weights
        int j = i - 4096;
        float v;
        if (j < 96)       v = m1_w[j];
        else if (j < 128) v = m1_b[j - 96];
        else if (j < 224) v = m2_w[j - 128];
        else if (j < 256) v = m2_b[j - 224];
        else if (j < 320) v = psi_w[j - 256];
        else              v = psi_b[0];
        g_gather[j] = v;
    }
}

__device__ __forceinline__ uint32_t smem_u32(const void* p) {
    uint32_t a;
    asm("{ .reg .u64 t; cvta.to.shared.u64 t, %1; cvt.u32.u64 %0, t; }" : "=r"(a) : "l"(p));
    return a;
}

__device__ __forceinline__ void mma_f16(float* d, uint32_t a0, uint32_t a1, uint32_t a2,
                                        uint32_t a3, uint32_t b0, uint32_t b1) {
    asm volatile(
        "mma.sync.aligned.m16n8k16.row.col.f32.f16.f16.f32 "
        "{%0,%1,%2,%3}, {%4,%5,%6,%7}, {%8,%9}, {%0,%1,%2,%3};"
        : "+f"(d[0]), "+f"(d[1]), "+f"(d[2]), "+f"(d[3])
        : "r"(a0), "r"(a1), "r"(a2), "r"(a3), "r"(b0), "r"(b1));
}

__global__ __launch_bounds__(256, 4)
void spil_kernel(const float* __restrict__ cxyz_g,  const float* __restrict__ cfeat_g,
                 const float* __restrict__ nxyz_g,  const float* __restrict__ nfeat_g,
                 const float* __restrict__ phi_b,   const float* __restrict__ theta_b,
                 const float* __restrict__ z_b,     float* __restrict__ out)
{
    extern __shared__ __align__(16) char smem[];
    float* sc = (float*)(smem + SM_SCAL);
    const uint32_t sbase = smem_u32(smem);
    const int tid = threadIdx.x;
    const int wid = tid >> 5, lid = tid & 31;
    const int g = lid >> 2, tg = lid & 3;
    const long g0 = (long)blockIdx.x * 4;

    // ================= P1: stage A (8 halves/thread, STS.128) + cf + r_l ==========
    {
        const float4* nf4 = (const float4*)(nfeat_g + g0 * (KNN * C_));
        #pragma unroll
        for (int it = 0; it < 8; it++) {
            int i = tid + it * 256;          // 0..2047
            float4 v0 = nf4[2 * i];
            float4 v1 = nf4[2 * i + 1];
            int f = i << 3;
            int r = f >> 7, c = f & 127;     // c multiple of 8
            __half2 h0 = __floats2half2_rn(v0.x, v0.y);
            __half2 h1 = __floats2half2_rn(v0.z, v0.w);
            __half2 h2 = __floats2half2_rn(v1.x, v1.y);
            __half2 h3 = __floats2half2_rn(v1.z, v1.w);
            uint4 uv = make_uint4(*(uint32_t*)&h0, *(uint32_t*)&h1,
                                  *(uint32_t*)&h2, *(uint32_t*)&h3);
            *(uint4*)(smem + SM_A + (r * SAH_STR + c) * 2) = uv;
        }
    }
    if (tid < 128) {
        // r_l for neighbor row r, s_i inline (all const-bank math)
        const int r = tid, pp = r >> 5;
        float nx = nxyz_g[g0 * 96 + r * 3], ny = nxyz_g[g0 * 96 + r * 3 + 1],
              nz = nxyz_g[g0 * 96 + r * 3 + 2];
        float cx = cxyz_g[(g0 + pp) * 3], cy = cxyz_g[(g0 + pp) * 3 + 1],
              cz = cxyz_g[(g0 + pp) * 3 + 2];
        float acc = C_PSB[0];
        #pragma unroll 8
        for (int j = 0; j < 32; j++) {
            float v = C_M1B[j] + cx * C_M1W[j] + cy * C_M1W[32 + j] + cz * C_M1W[64 + j];
            acc = fmaf(fmaxf(v, 0.f), C_PSW[j], acc);
        }
        #pragma unroll 8
        for (int j = 0; j < 32; j++) {
            float v = C_M2B[j] + nx * C_M2W[j] + ny * C_M2W[32 + j] + nz * C_M2W[64 + j];
            acc = fmaf(fmaxf(v, 0.f), C_PSW[32 + j], acc);
        }
        float rl = fmaxf(acc, 0.f);
        float dx = cx - nx, dy = cy - ny, dz = cz - nz;
        if (cz == nz && dx * dx + dy * dy + dz * dz > 0.0016f) rl = 0.f;  // SPIL mask
        sc[OF_RL + r] = rl;
    } else {
        // stage cf (4 rows x 128 cols fp16) into SM_CF rows 0-3
        int i = tid - 128;           // 0..127
        int row = i >> 5, c0 = (i & 31) * 4;
        float4 v = *(const float4*)&cfeat_g[(g0 + row) * C_ + c0];
        __half2 h0 = __floats2half2_rn(v.x, v.y);
        __half2 h1 = __floats2half2_rn(v.z, v.w);
        uint2 uv = make_uint2(*(uint32_t*)&h0, *(uint32_t*)&h1);
        *(uint2*)(smem + SM_CF + (row * SAH_STR + c0) * 2) = uv;
    }
    __syncthreads();

    // ================= P2: MMAs ===================================================
    const int p = wid >> 1, nh = wid & 1;

    // cf @ phi_w on warps 4-7 (m16n16 each): balances extra load to 12.5%/warp
    if (wid >= 4) {
        const int jt = wid - 4;      // n16 block 0..3
        float dcf[2][4];
        #pragma unroll
        for (int t = 0; t < 2; t++)
            #pragma unroll
            for (int j = 0; j < 4; j++) dcf[t][j] = 0.f;
        const uint32_t cfa = sbase + SM_CF
            + (uint32_t)((((lid & 15)) * SAH_STR + ((lid >> 4) * 8)) * 2);
        const float4* Bp = g_Bp + jt * 32 + lid;
        #pragma unroll
        for (int kc = 0; kc < 8; kc++) {
            uint32_t a0, a1, a2, a3;
            asm volatile("ldmatrix.sync.aligned.m8n8.x4.shared.b16 {%0,%1,%2,%3}, [%4];"
                         : "=r"(a0), "=r"(a1), "=r"(a2), "=r"(a3)
                         : "r"(cfa + (uint32_t)(kc * 32)));
            float4 bv = __ldg(Bp + kc * 128);
            mma_f16(dcf[0], a0, a1, a2, a3, __float_as_uint(bv.x), __float_as_uint(bv.y));
            mma_f16(dcf[1], a0, a1, a2, a3, __float_as_uint(bv.z), __float_as_uint(bv.w));
        }
        if (g < 4) {   // row g = point g; FI = relu(dcf + phi_b)
            #pragma unroll
            for (int t = 0; t < 2; t++) {
                int h0 = jt * 16 + t * 8 + 2 * tg;
                float2 pb = *(const float2*)&phi_b[h0];
                sc[OF_FI + g * 64 + h0]     = fmaxf(dcf[t][0] + pb.x, 0.f);
                sc[OF_FI + g * 64 + h0 + 1] = fmaxf(dcf[t][1] + pb.y, 0.f);
            }
        }
    }

    // theta MMA m32n32 (warp: point p, n-half nh) — all 8 warps
    float dacc[2][4][4];
    #pragma unroll
    for (int mt = 0; mt < 2; mt++)
        #pragma unroll
        for (int t = 0; t < 4; t++)
            #pragma unroll
            for (int j = 0; j < 4; j++) dacc[mt][t][j] = 0.f;
    {
        const uint32_t aa0 = sbase + SM_A
            + (uint32_t)(((p * 32 + (lid & 15)) * SAH_STR + ((lid >> 4) * 8)) * 2);
        const uint32_t aa1 = aa0 + (uint32_t)(16 * SAH_STR * 2);
        const float4* Bh0 = g_Bh + (2 * nh) * 32 + lid;
        const float4* Bh1 = Bh0 + 32;
        #pragma unroll
        for (int kc = 0; kc < 8; kc++) {
            uint32_t x0, x1, x2, x3, y0, y1, y2, y3;
            asm volatile("ldmatrix.sync.aligned.m8n8.x4.shared.b16 {%0,%1,%2,%3}, [%4];"
                         : "=r"(x0), "=r"(x1), "=r"(x2), "=r"(x3)
                         : "r"(aa0 + (uint32_t)(kc * 32)));
            asm volatile("ldmatrix.sync.aligned.m8n8.x4.shared.b16 {%0,%1,%2,%3}, [%4];"
                         : "=r"(y0), "=r"(y1), "=r"(y2), "=r"(y3)
                         : "r"(aa1 + (uint32_t)(kc * 32)));
            float4 bv0 = __ldg(Bh0 + kc * 128);
            float4 bv1 = __ldg(Bh1 + kc * 128);
            uint32_t b0 = __float_as_uint(bv0.x), b1 = __float_as_uint(bv0.y);
            uint32_t b2 = __float_as_uint(bv0.z), b3 = __float_as_uint(bv0.w);
            uint32_t b4 = __float_as_uint(bv1.x), b5 = __float_as_uint(bv1.y);
            uint32_t b6 = __float_as_uint(bv1.z), b7 = __float_as_uint(bv1.w);
            mma_f16(dacc[0][0], x0, x1, x2, x3, b0, b1);
            mma_f16(dacc[0][1], x0, x1, x2, x3, b2, b3);
            mma_f16(dacc[0][2], x0, x1, x2, x3, b4, b5);
            mma_f16(dacc[0][3], x0, x1, x2, x3, b6, b7);
            mma_f16(dacc[1][0], y0, y1, y2, y3, b0, b1);
            mma_f16(dacc[1][1], y0, y1, y2, y3, b2, b3);
            mma_f16(dacc[1][2], y0, y1, y2, y3, b4, b5);
            mma_f16(dacc[1][3], y0, y1, y2, y3, b6, b7);
        }
    }
    __syncthreads();   // FI ready for everyone

    // ================= P3: rf dot from dacc + FI; quad-reduce + transpose =========
    {
        float rfp[4] = {0.f, 0.f, 0.f, 0.f};
        #pragma unroll
        for (int t = 0; t < 4; t++) {
            int h0 = nh * 32 + t * 8 + 2 * tg;
            float2 fi = *(const float2*)&sc[OF_FI + p * 64 + h0];
            float2 tb = *(const float2*)&theta_b[h0];
            rfp[0] = fmaf(fi.x, fmaxf(dacc[0][t][0] + tb.x, 0.f),
                     fmaf(fi.y, fmaxf(dacc[0][t][1] + tb.y, 0.f), rfp[0]));
            rfp[1] = fmaf(fi.x, fmaxf(dacc[0][t][2] + tb.x, 0.f),
                     fmaf(fi.y, fmaxf(dacc[0][t][3] + tb.y, 0.f), rfp[1]));
            rfp[2] = fmaf(fi.x, fmaxf(dacc[1][t][0] + tb.x, 0.f),
                     fmaf(fi.y, fmaxf(dacc[1][t][1] + tb.y, 0.f), rfp[2]));
            rfp[3] = fmaf(fi.x, fmaxf(dacc[1][t][2] + tb.x, 0.f),
                     fmaf(fi.y, fmaxf(dacc[1][t][3] + tb.y, 0.f), rfp[3]));
        }
        #pragma unroll
        for (int j = 0; j < 4; j++) {
            rfp[j] += __shfl_xor_sync(0xFFFFFFFFu, rfp[j], 1);
            rfp[j] += __shfl_xor_sync(0xFFFFFFFFu, rfp[j], 2);
        }
        sc[OF_RFP + wid * 32 + g + 8 * tg] = rfp[tg];
    }
    __syncthreads();

    // ================= P4: softmax (warps 0-3), W stored as fp16 ==================
    __half* Wh = (__half*)(sc + OF_W);
    if (wid < 4) {
        const int k = lid, r = wid * KNN + k;
        float rf = (sc[OF_RFP + (2 * wid) * 32 + k] + sc[OF_RFP + (2 * wid + 1) * 32 + k])
                 * 0.125f;   // 1/sqrt(H)
        float rl = sc[OF_RL + r];
        float m = rf;
        #pragma unroll
        for (int o = 16; o; o >>= 1) m = fmaxf(m, __shfl_xor_sync(0xFFFFFFFFu, m, o));
        float e = rl * __expf(rf - m);
        float s = e;
        #pragma unroll
        for (int o = 16; o; o >>= 1) s += __shfl_xor_sync(0xFFFFFFFFu, s, o);
        float inv = 1.f / (s + 1e-8f);
        Wh[r] = __float2half(e * inv);
        if (k == 0) sc[OF_SW + wid] = s * inv;
    }
    __syncthreads();

    // ================= P5: MMA-2  agg[4,128] = W @ nf-tile ========================
    __half* aggh = (__half*)(sc + OF_FI);  // FI dead after P3
    {
        float d2[2][4];
        #pragma unroll
        for (int t = 0; t < 2; t++)
            #pragma unroll
            for (int j = 0; j < 4; j++) d2[t][j] = 0.f;
        const int row_l = ((lid >> 3) & 1) * 8 + (lid & 7);
        const uint32_t baddr = sbase + SM_A
            + (uint32_t)((row_l * SAH_STR + wid * 16 + (lid >> 4) * 8) * 2);
        #pragma unroll
        for (int kc = 0; kc < 8; kc++) {
            uint32_t b0, b1, b2, b3;
            asm volatile("ldmatrix.sync.aligned.m8n8.x4.trans.shared.b16 {%0,%1,%2,%3}, [%4];"
                         : "=r"(b0), "=r"(b1), "=r"(b2), "=r"(b3)
                         : "r"(baddr + (uint32_t)(kc * 16 * SAH_STR * 2)));
            uint32_t a0 = 0u, a2 = 0u;
            if (g == (kc >> 1)) {
                const __half* wp = Wh + g * 32 + (kc & 1) * 16 + 2 * tg;
                a0 = *(const uint32_t*)wp;
                a2 = *(const uint32_t*)(wp + 8);
            }
            mma_f16(d2[0], a0, 0u, a2, 0u, b0, b1);
            mma_f16(d2[1], a0, 0u, a2, 0u, b2, b3);
        }
        if (g < 4) {
            #pragma unroll
            for (int t = 0; t < 2; t++) {
                __half2 hv = __floats2half2_rn(d2[t][0], d2[t][1]);
                *(uint32_t*)&aggh[g * 128 + wid * 16 + t * 8 + 2 * tg] = *(uint32_t*)&hv;
            }
        }
    }
    __syncthreads();

    // ================= P6: MMA-3  out[4,64] = agg @ z_w  (+ sumW*z_b) =============
    {
        float d3[4] = {0.f, 0.f, 0.f, 0.f};
        const float2* Bz = g_Bz + wid * 32 + lid;
        #pragma unroll
        for (int kc = 0; kc < 8; kc++) {
            uint32_t a0 = 0u, a2 = 0u;
            if (g < 4) {
                const __half* ap = aggh + g * 128 + kc * 16 + 2 * tg;
                a0 = *(const uint32_t*)ap;
                a2 = *(const uint32_t*)(ap + 8);
            }
            float2 bv = __ldg(Bz + kc * 256);
            mma_f16(d3, a0, 0u, a2, 0u, __float_as_uint(bv.x), __float_as_uint(bv.y));
        }
        if (g < 4) {
            int h0 = wid * 8 + 2 * tg;
            float sw = sc[OF_SW + g];
            float2 o;
            o.x = d3[0] + sw * z_b[h0];
            o.y = d3[1] + sw * z_b[h0 + 1];
            *(float2*)&out[(g0 + g) * H_ + h0] = o;
        }
    }
}

extern "C" void kernel_launch(void* const* d_in, const int* in_sizes, int n_in,
                              void* d_out, int out_size) {
    (void)in_sizes; (void)n_in; (void)out_size;
    cudaFuncSetAttribute(spil_kernel, cudaFuncAttributeMaxDynamicSharedMemorySize, SMEM_BYTES);

    pack_weights<<<18, 256>>>(
        (const float*)d_in[6],  (const float*)d_in[4],  (const float*)d_in[14],
        (const float*)d_in[8],  (const float*)d_in[9],
        (const float*)d_in[10], (const float*)d_in[11],
        (const float*)d_in[12], (const float*)d_in[13]);

    void *dstc, *srcg;
    cudaGetSymbolAddress(&dstc, C_ALL);
    cudaGetSymbolAddress(&srcg, g_gather);
    cudaMemcpyAsync(dstc, srcg, 321 * 4, cudaMemcpyDeviceToDevice);

    spil_kernel<<<8192, 256, SMEM_BYTES>>>(
        (const float*)d_in[0], (const float*)d_in[1],
        (const float*)d_in[2], (const float*)d_in[3],
        (const float*)d_in[5], (const float*)d_in[7],
        (const float*)d_in[15],
        (float*)d_out);
}